// round 10
// baseline (speedup 1.0000x reference)
#include <cuda_runtime.h>
#include <cuda_bf16.h>
#include <math.h>
#include <stdint.h>

// Problem constants
#define T_TOK 4096
#define D_DIM 512
#define E_NUM 8
#define F_DIM 2048
#define DF_DIM 64
#define CAP   9216          // 72*128: 2T=8192 slots + worst-case per-expert 128-pad
#define MTILES 72
#define RBLOCKS 512

// SMEM stage: A tile 16KB ([m=128][128B: hi64|lo64]) + Bhi 8KB + Blo 8KB ([k=32][256B])
#define A_TILE_BYTES 16384
#define B_TILE_BYTES 8192
#define STAGE_BYTES (A_TILE_BYTES + 2*B_TILE_BYTES)   // 32KB
#define DSMEM_BYTES (2*STAGE_BYTES)                    // 64KB double-buffered

// ---------------- scratch (device globals) — 113.4 MB, proven-safe footprint ----------------
__device__ int   g_counts[E_NUM];
__device__ int   g_fill[E_NUM];
__device__ int   g_offpad[E_NUM + 1];
__device__ int   g_tile_expert[MTILES];
__device__ int   g_slot_token[CAP];
__device__ int   g_slot_expert[CAP];
__device__ float g_slot_w[CAP];
__device__ int   g_token_slot[T_TOK * 2];
__device__ int   g_tok_idx[T_TOK * 2];
__device__ float g_tok_w[T_TOK * 2];
__device__ float g_probs_partial[RBLOCKS * E_NUM];

__device__ __align__(16) __nv_bfloat16 g_ah[CAP * D_DIM];   // gathered x (+side), bf16 hi
__device__ __align__(16) __nv_bfloat16 g_al[CAP * D_DIM];   // lo residual
__device__ __align__(16) __nv_bfloat16 g_hh[CAP * F_DIM];   // gelu output hi
__device__ __align__(16) __nv_bfloat16 g_hl[CAP * F_DIM];   // gelu output lo
__device__ __align__(16) float g_outs[CAP * D_DIM];         // GEMM2 result (no bias)

// ---------------- helpers ----------------
__device__ __forceinline__ uint32_t smem_u32(const void* p) {
    uint32_t a;
    asm("{ .reg .u64 t; cvta.to.shared.u64 t, %1; cvt.u32.u64 %0, t; }" : "=r"(a) : "l"(p));
    return a;
}
#define SWZ128(o) ((o) ^ (((o) >> 3) & 0x70))

#define LDSM4(r, addr) \
    asm volatile("ldmatrix.sync.aligned.m8n8.x4.shared.b16 {%0,%1,%2,%3}, [%4];" \
        : "=r"((r)[0]), "=r"((r)[1]), "=r"((r)[2]), "=r"((r)[3]) : "r"(addr))
#define LDSM2T(r, addr) \
    asm volatile("ldmatrix.sync.aligned.m8n8.x2.trans.shared.b16 {%0,%1}, [%2];" \
        : "=r"((r)[0]), "=r"((r)[1]) : "r"(addr))
#define MMA_BF16(d, a, b) \
    asm volatile("mma.sync.aligned.m16n8k16.row.col.f32.bf16.bf16.f32 " \
        "{%0,%1,%2,%3}, {%4,%5,%6,%7}, {%8,%9}, {%0,%1,%2,%3};" \
        : "+f"((d)[0]), "+f"((d)[1]), "+f"((d)[2]), "+f"((d)[3]) \
        : "r"((a)[0]), "r"((a)[1]), "r"((a)[2]), "r"((a)[3]), "r"((b)[0]), "r"((b)[1]))
#define CP_ASYNC16(dst, src) \
    asm volatile("cp.async.cg.shared.global [%0], [%1], 16;" :: "r"(dst), "l"(src) : "memory")
#define CP_COMMIT() asm volatile("cp.async.commit_group;" ::: "memory")
#define CP_WAIT(n)  asm volatile("cp.async.wait_group %0;" :: "n"(n) : "memory")

__device__ __forceinline__ float gelu_tanh(float v) {
    float c = 0.7978845608028654f * (v + 0.044715f * v * v * v);
    return 0.5f * v * (1.0f + tanhf(c));
}

// split f32x4 -> bf16 hi pair + lo pair
__device__ __forceinline__ void split4(float4 f, uint2& hv, uint2& lv) {
    __nv_bfloat162 h01 = __floats2bfloat162_rn(f.x, f.y);
    __nv_bfloat162 h23 = __floats2bfloat162_rn(f.z, f.w);
    __nv_bfloat162 l01 = __floats2bfloat162_rn(f.x - __bfloat162float(__low2bfloat16(h01)),
                                               f.y - __bfloat162float(__high2bfloat16(h01)));
    __nv_bfloat162 l23 = __floats2bfloat162_rn(f.z - __bfloat162float(__low2bfloat16(h23)),
                                               f.w - __bfloat162float(__high2bfloat16(h23)));
    hv = make_uint2(*(uint32_t*)&h01, *(uint32_t*)&h23);
    lv = make_uint2(*(uint32_t*)&l01, *(uint32_t*)&l23);
}

// ---------------- init ----------------
__global__ void init_kernel() {
    int i = blockIdx.x * 256 + threadIdx.x;
    if (i < CAP) g_slot_token[i] = -1;
    if (i < E_NUM) { g_counts[i] = 0; g_fill[i] = 0; }
}

// ---------------- router ----------------
__global__ __launch_bounds__(256) void router_kernel(const float* __restrict__ x,
                                                     const float* __restrict__ Wr) {
    __shared__ float sWr[D_DIM * E_NUM];
    __shared__ float sprobs[8][E_NUM];
    int tid = threadIdx.x;
    #pragma unroll
    for (int i = tid; i < D_DIM * E_NUM; i += 256) sWr[i] = Wr[i];
    __syncthreads();

    int warp = tid >> 5, lane = tid & 31;
    int t = blockIdx.x * 8 + warp;
    const float* xr = x + (size_t)t * D_DIM;

    float acc[E_NUM];
    #pragma unroll
    for (int e = 0; e < E_NUM; e++) acc[e] = 0.f;
    for (int k = lane; k < D_DIM; k += 32) {
        float xv = xr[k];
        const float* w = sWr + k * E_NUM;
        #pragma unroll
        for (int e = 0; e < E_NUM; e++) acc[e] += xv * w[e];
    }
    #pragma unroll
    for (int e = 0; e < E_NUM; e++) {
        float v = acc[e];
        #pragma unroll
        for (int off = 16; off >= 1; off >>= 1) v += __shfl_xor_sync(0xffffffffu, v, off);
        acc[e] = v;
    }
    if (lane == 0) {
        float mx = acc[0];
        #pragma unroll
        for (int e = 1; e < E_NUM; e++) mx = fmaxf(mx, acc[e]);
        float p[E_NUM]; float s = 0.f;
        #pragma unroll
        for (int e = 0; e < E_NUM; e++) { p[e] = expf(acc[e] - mx); s += p[e]; }
        float inv = 1.f / s;
        #pragma unroll
        for (int e = 0; e < E_NUM; e++) p[e] *= inv;
        int i0 = 0;
        #pragma unroll
        for (int e = 1; e < E_NUM; e++) if (p[e] > p[i0]) i0 = e;
        int i1 = -1;
        #pragma unroll
        for (int e = 0; e < E_NUM; e++) {
            if (e == i0) continue;
            if (i1 < 0 || p[e] > p[i1]) i1 = e;
        }
        float w0 = p[i0], w1 = p[i1];
        float wn = 1.f / (w0 + w1);
        g_tok_idx[2 * t + 0] = i0; g_tok_w[2 * t + 0] = w0 * wn;
        g_tok_idx[2 * t + 1] = i1; g_tok_w[2 * t + 1] = w1 * wn;
        atomicAdd(&g_counts[i0], 1);
        atomicAdd(&g_counts[i1], 1);
        #pragma unroll
        for (int e = 0; e < E_NUM; e++) sprobs[warp][e] = p[e];
    }
    __syncthreads();
    if (tid < E_NUM) {
        float s = 0.f;
        #pragma unroll
        for (int w = 0; w < 8; w++) s += sprobs[w][tid];
        g_probs_partial[blockIdx.x * E_NUM + tid] = s;
    }
}

// ---------------- scan ----------------
__global__ void scan_kernel(float* aux_out) {
    __shared__ float psum[E_NUM];
    int tid = threadIdx.x;
    if (tid < E_NUM) {
        float s = 0.f;
        for (int b = 0; b < RBLOCKS; b++) s += g_probs_partial[b * E_NUM + tid];
        psum[tid] = s;
    }
    __syncthreads();
    if (tid == 0) {
        int off = 0;
        for (int e = 0; e < E_NUM; e++) {
            g_offpad[e] = off;
            off += ((g_counts[e] + 127) / 128) * 128;
        }
        g_offpad[E_NUM] = off;
        for (int tile = 0; tile < MTILES; tile++) {
            int row = tile * 128;
            int ex = E_NUM - 1;
            for (int q = 0; q < E_NUM; q++) {
                if (row >= g_offpad[q] && row < g_offpad[q + 1]) { ex = q; break; }
            }
            g_tile_expert[tile] = ex;
        }
        float aux = 0.f;
        for (int e = 0; e < E_NUM; e++)
            aux += ((float)g_counts[e] / (float)T_TOK) * (psum[e] / (float)T_TOK);
        aux *= (float)E_NUM;
        if (aux_out) aux_out[0] = aux;
    }
}

// ---------------- assign ----------------
__global__ void assign_kernel() {
    int t = blockIdx.x * 256 + threadIdx.x;
    if (t >= T_TOK) return;
    #pragma unroll
    for (int j = 0; j < 2; j++) {
        int e = g_tok_idx[2 * t + j];
        int pos = atomicAdd(&g_fill[e], 1);
        int s = g_offpad[e] + pos;
        g_slot_token[s] = t;
        g_slot_expert[s] = e;
        g_slot_w[s] = g_tok_w[2 * t + j];
        g_token_slot[2 * t + j] = s;
    }
}

// ---------------- gather: xg[slot] -> bf16 hi/lo ----------------
__global__ __launch_bounds__(128) void gather_kernel(const float* __restrict__ x,
                                                     const float* __restrict__ flow,
                                                     const float* __restrict__ avgq,
                                                     const float* __restrict__ deltas,
                                                     const float* __restrict__ Wf,
                                                     const float* __restrict__ Wd) {
    __shared__ float side[DF_DIM];
    int slot = blockIdx.x;
    int t = g_slot_token[slot];
    int d4 = threadIdx.x;  // 128 threads * 4 elems
    uint2* dsth = (uint2*)(g_ah + (size_t)slot * D_DIM + d4 * 4);
    uint2* dstl = (uint2*)(g_al + (size_t)slot * D_DIM + d4 * 4);
    if (t < 0) {
        *dsth = make_uint2(0u, 0u);
        *dstl = make_uint2(0u, 0u);
        return;
    }
    int e = g_slot_expert[slot];
    float4 v = ((const float4*)(x + (size_t)t * D_DIM))[d4];
    if (e == 0 || e == 4) {
        const float* srow = (e == 0 ? flow : deltas) + (size_t)t * DF_DIM;
        if (threadIdx.x < DF_DIM) side[threadIdx.x] = srow[threadIdx.x];
        __syncthreads();
        const float* W = (e == 0 ? Wf : Wd);
        int d0 = d4 * 4;
        #pragma unroll 8
        for (int k = 0; k < DF_DIM; k++) {
            float s = side[k];
            float4 w = *(const float4*)(W + (size_t)k * D_DIM + d0);
            v.x += s * w.x; v.y += s * w.y; v.z += s * w.z; v.w += s * w.w;
        }
    } else if (e == 3) {
        float4 q = ((const float4*)(avgq + (size_t)t * D_DIM))[d4];
        v.x += q.x; v.y += q.y; v.z += q.z; v.w += q.w;
    }
    uint2 hv, lv;
    split4(v, hv, lv);
    *dsth = hv;
    *dstl = lv;
}

// ---------------- grouped GEMM via mma.sync m16n8k16 bf16, 3-term split ----------------
// Block: 512 thr = 16 warps (4m x 4n), warp tile 32x32, block tile 128x128, K-chunk 32.
// 16 warps resident -> 4 warps/SMSP for latency hiding.
// A: cp.async bf16 hi/lo, SMEM [m=128][128B hi|lo] SW128, non-trans ldmatrix.x4.
// B: fp32 weights loaded directly, converted bf16 hi/lo in-flight,
//    SMEM [k=32][256B n-major], swizzle byte(k,Y) = k*256 + (Y ^ ((k&7)<<4)), ldmatrix.x2.trans.
template <int KTOT, bool FIRST>
__global__ __launch_bounds__(512) void gemm_mma(const float* __restrict__ Wsrc,
                                                const float* __restrict__ bias) {
    constexpr int NTOT = FIRST ? F_DIM : D_DIM;
    constexpr int NCH = KTOT / 32;
    extern __shared__ char dsm[];

    const int mtile = blockIdx.y;
    if (mtile * 128 >= g_offpad[E_NUM]) return;   // early-exit unused padded tiles

    const int tid = threadIdx.x;
    const int wid = tid >> 5, lane = tid & 31;
    const int wm = wid >> 2, wn = wid & 3;        // 4x4 warp grid, warp tile 32x32
    const int ntile = blockIdx.x;
    const int e = g_tile_expert[mtile];

    const __nv_bfloat16* Ah = (FIRST ? g_ah : g_hh) + (size_t)(mtile * 128) * KTOT;
    const __nv_bfloat16* Al = (FIRST ? g_al : g_hl) + (size_t)(mtile * 128) * KTOT;
    const float* Bw = Wsrc + (size_t)e * KTOT * NTOT + ntile * 128;   // [k][n] fp32, n contig

    const uint32_t smb = smem_u32(dsm);

    // ---- A staging plan (cp.async): 1024 16B-units/chunk, 2 per thread (rows r0, r0+64).
    const int r0  = tid >> 3;        // 0..63
    const int sub = tid & 7;
    const int halfA = sub >> 2, ku = sub & 3;
    const __nv_bfloat16* pA = (halfA ? Al : Ah) + (size_t)r0 * KTOT + ku * 8;
    const uint32_t dA0 = SWZ128((uint32_t)(r0 * 128 + halfA * 64 + ku * 16));
    // SWZ128 invariant under +8192 (row += 64): dst_i = dA0 + i*8192.

    // ---- B staging plan: thread covers row krow, floats [seg*8, seg*8+8).
    const int krow = tid >> 4;       // 0..31
    const int seg  = tid & 15;       // 16 segments of 8 floats
    const float* pB = Bw + (size_t)krow * NTOT + seg * 8;
    const uint32_t dBrow = (uint32_t)(krow * 256);
    const uint32_t maskB = ((uint32_t)(krow & 7)) << 4;
    // 8B stores at: dBrow + ((seg*16 + {0,8}) ^ maskB)   [always < 256]

    float acc[2][4][4];
    #pragma unroll
    for (int mf = 0; mf < 2; mf++)
        #pragma unroll
        for (int nf = 0; nf < 4; nf++)
            #pragma unroll
            for (int k = 0; k < 4; k++) acc[mf][nf][k] = 0.f;

    // ---- prologue: chunk 0 -> buffer 0
    {
        #pragma unroll
        for (int i = 0; i < 2; i++)
            CP_ASYNC16(smb + dA0 + i * 8192, pA + (size_t)i * 64 * KTOT);
        CP_COMMIT();
        char* bh = dsm + A_TILE_BYTES;
        char* bl = bh + B_TILE_BYTES;
        float4 f1 = *(const float4*)(pB);
        float4 f2 = *(const float4*)(pB + 4);
        uint2 h1, l1, h2, l2;
        split4(f1, h1, l1);
        split4(f2, h2, l2);
        uint32_t o1 = dBrow + (((uint32_t)(seg * 16)) ^ maskB);
        uint32_t o2 = dBrow + (((uint32_t)(seg * 16 + 8)) ^ maskB);
        *(uint2*)(bh + o1) = h1; *(uint2*)(bl + o1) = l1;
        *(uint2*)(bh + o2) = h2; *(uint2*)(bl + o2) = l2;
        CP_WAIT(0);
    }
    __syncthreads();

    #pragma unroll 1
    for (int c = 0; c < NCH; c++) {
        const int buf = c & 1;
        float4 bq1, bq2;
        if (c + 1 < NCH) {
            const uint32_t nbA = smb + (buf ^ 1) * STAGE_BYTES;
            #pragma unroll
            for (int i = 0; i < 2; i++)
                CP_ASYNC16(nbA + dA0 + i * 8192, pA + (size_t)i * 64 * KTOT + (c + 1) * 32);
            CP_COMMIT();
            const float* pBn = pB + (size_t)(c + 1) * 32 * NTOT;
            bq1 = *(const float4*)(pBn);
            bq2 = *(const float4*)(pBn + 4);
        }

        // ---- compute chunk c
        const uint32_t At  = smb + buf * STAGE_BYTES;
        const uint32_t Bth = At + A_TILE_BYTES;
        const uint32_t Btl = Bth + B_TILE_BYTES;
        #pragma unroll
        for (int s = 0; s < 2; s++) {
            uint32_t ah[2][4], al[2][4];
            #pragma unroll
            for (int mf = 0; mf < 2; mf++) {
                int row = wm * 32 + mf * 16 + (lane & 15);
                int u = lane >> 4;
                uint32_t off = (uint32_t)(row * 128 + s * 32 + u * 16);
                LDSM4(ah[mf], At + SWZ128(off));
                LDSM4(al[mf], At + SWZ128(off + 64));
            }
            #pragma unroll
            for (int nf = 0; nf < 4; nf++) {
                uint32_t bh[2], bl[2];
                int kk = s * 16 + (lane & 15);
                uint32_t boff = (uint32_t)(kk * 256) +
                                (((uint32_t)(wn * 64 + nf * 16)) ^ ((uint32_t)(lane & 7) << 4));
                LDSM2T(bh, Bth + boff);
                LDSM2T(bl, Btl + boff);
                #pragma unroll
                for (int mf = 0; mf < 2; mf++) {
                    MMA_BF16(acc[mf][nf], ah[mf], bh);
                    MMA_BF16(acc[mf][nf], ah[mf], bl);
                    MMA_BF16(acc[mf][nf], al[mf], bh);
                }
            }
        }

        if (c + 1 < NCH) {
            char* nbh = dsm + (buf ^ 1) * STAGE_BYTES + A_TILE_BYTES;
            char* nbl = nbh + B_TILE_BYTES;
            uint2 h1, l1, h2, l2;
            split4(bq1, h1, l1);
            split4(bq2, h2, l2);
            uint32_t o1 = dBrow + (((uint32_t)(seg * 16)) ^ maskB);
            uint32_t o2 = dBrow + (((uint32_t)(seg * 16 + 8)) ^ maskB);
            *(uint2*)(nbh + o1) = h1; *(uint2*)(nbl + o1) = l1;
            *(uint2*)(nbh + o2) = h2; *(uint2*)(nbl + o2) = l2;
            CP_WAIT(0);
        }
        __syncthreads();
    }

    // ---- epilogue
    #pragma unroll
    for (int mf = 0; mf < 2; mf++) {
        int row0 = mtile * 128 + wm * 32 + mf * 16 + (lane >> 2);
        int row1 = row0 + 8;
        #pragma unroll
        for (int nf = 0; nf < 4; nf++) {
            int n = ntile * 128 + wn * 32 + nf * 8 + 2 * (lane & 3);
            if (FIRST) {
                float b0v = bias[(size_t)e * NTOT + n];
                float b1v = bias[(size_t)e * NTOT + n + 1];
                #pragma unroll
                for (int h = 0; h < 2; h++) {
                    int row = h ? row1 : row0;
                    float v0 = gelu_tanh(acc[mf][nf][2 * h + 0] + b0v);
                    float v1 = gelu_tanh(acc[mf][nf][2 * h + 1] + b1v);
                    __nv_bfloat162 h2 = __floats2bfloat162_rn(v0, v1);
                    float f0 = __bfloat162float(__low2bfloat16(h2));
                    float f1 = __bfloat162float(__high2bfloat16(h2));
                    __nv_bfloat162 l2 = __floats2bfloat162_rn(v0 - f0, v1 - f1);
                    *(uint32_t*)(g_hh + (size_t)row * F_DIM + n) = *(uint32_t*)&h2;
                    *(uint32_t*)(g_hl + (size_t)row * F_DIM + n) = *(uint32_t*)&l2;
                }
            } else {
                *(float2*)(g_outs + (size_t)row0 * D_DIM + n) =
                    make_float2(acc[mf][nf][0], acc[mf][nf][1]);
                *(float2*)(g_outs + (size_t)row1 * D_DIM + n) =
                    make_float2(acc[mf][nf][2], acc[mf][nf][3]);
            }
        }
    }
}

// ---------------- combine ----------------
__global__ __launch_bounds__(128) void combine_kernel(const float* __restrict__ b2,
                                                      float* __restrict__ out) {
    int t = blockIdx.x;
    int d4 = threadIdx.x;
    int s0 = g_token_slot[2 * t + 0];
    int s1 = g_token_slot[2 * t + 1];
    int e0 = g_slot_expert[s0], e1 = g_slot_expert[s1];
    float w0 = g_slot_w[s0], w1 = g_slot_w[s1];
    float4 o0 = ((const float4*)(g_outs + (size_t)s0 * D_DIM))[d4];
    float4 o1 = ((const float4*)(g_outs + (size_t)s1 * D_DIM))[d4];
    float4 c0 = ((const float4*)(b2 + (size_t)e0 * D_DIM))[d4];
    float4 c1 = ((const float4*)(b2 + (size_t)e1 * D_DIM))[d4];
    float4 r;
    r.x = w0 * (o0.x + c0.x) + w1 * (o1.x + c1.x);
    r.y = w0 * (o0.y + c0.y) + w1 * (o1.y + c1.y);
    r.z = w0 * (o0.z + c0.z) + w1 * (o1.z + c1.z);
    r.w = w0 * (o0.w + c0.w) + w1 * (o1.w + c1.w);
    ((float4*)(out + (size_t)t * D_DIM))[d4] = r;
}

// ---------------- launch ----------------
extern "C" void kernel_launch(void* const* d_in, const int* in_sizes, int n_in,
                              void* d_out, int out_size) {
    const float* x      = (const float*)d_in[0];
    const float* flow   = (const float*)d_in[1];
    const float* avgq   = (const float*)d_in[2];
    const float* deltas = (const float*)d_in[3];
    const float* Wr     = (const float*)d_in[4];
    const float* W1     = (const float*)d_in[5];
    const float* b1     = (const float*)d_in[6];
    const float* W2     = (const float*)d_in[7];
    const float* b2     = (const float*)d_in[8];
    const float* Wf     = (const float*)d_in[9];
    const float* Wd     = (const float*)d_in[10];
    float* out = (float*)d_out;

    float* aux_ptr = (out_size > T_TOK * D_DIM) ? (out + (size_t)T_TOK * D_DIM) : nullptr;

    cudaFuncSetAttribute(gemm_mma<D_DIM, true>,  cudaFuncAttributeMaxDynamicSharedMemorySize, DSMEM_BYTES);
    cudaFuncSetAttribute(gemm_mma<F_DIM, false>, cudaFuncAttributeMaxDynamicSharedMemorySize, DSMEM_BYTES);

    init_kernel<<<(CAP + 255) / 256, 256>>>();
    router_kernel<<<RBLOCKS, 256>>>(x, Wr);
    scan_kernel<<<1, 256>>>(aux_ptr);
    assign_kernel<<<(T_TOK + 255) / 256, 256>>>();
    gather_kernel<<<CAP, 128>>>(x, flow, avgq, deltas, Wf, Wd);
    gemm_mma<D_DIM, true><<<dim3(F_DIM / 128, MTILES), 512, DSMEM_BYTES>>>(W1, b1);
    gemm_mma<F_DIM, false><<<dim3(D_DIM / 128, MTILES), 512, DSMEM_BYTES>>>(W2, nullptr);
    combine_kernel<<<T_TOK, 128>>>(b2, out);
}

// round 11
// speedup vs baseline: 1.5149x; 1.5149x over previous
#include <cuda_runtime.h>
#include <cuda_fp16.h>
#include <math.h>
#include <stdint.h>

// Problem constants
#define T_TOK 4096
#define D_DIM 512
#define E_NUM 8
#define F_DIM 2048
#define DF_DIM 64
#define CAP   9216          // 72*128: 2T=8192 slots + worst-case per-expert 128-pad
#define MTILES 72
#define RBLOCKS 512

// SMEM stage (K-chunk 64): A 16KB ([m=128][128B fp16 k0..63] SW128) + B 16KB ([k=64][256B n-major])
#define A_TILE_BYTES 16384
#define B_TILE_BYTES 16384
#define STAGE_BYTES (A_TILE_BYTES + B_TILE_BYTES)     // 32KB
#define DSMEM_BYTES (2*STAGE_BYTES)                    // 64KB double-buffered

// ---------------- scratch (device globals) — ~66 MB ----------------
__device__ int   g_counts[E_NUM];
__device__ int   g_fill[E_NUM];
__device__ int   g_offpad[E_NUM + 1];
__device__ int   g_tile_expert[MTILES];
__device__ int   g_slot_token[CAP];
__device__ int   g_slot_expert[CAP];
__device__ float g_slot_w[CAP];
__device__ int   g_token_slot[T_TOK * 2];
__device__ int   g_tok_idx[T_TOK * 2];
__device__ float g_tok_w[T_TOK * 2];
__device__ float g_probs_partial[RBLOCKS * E_NUM];

__device__ __align__(16) __half g_ah[CAP * D_DIM];   // gathered x (+side), fp16
__device__ __align__(16) __half g_hh[CAP * F_DIM];   // gelu output, fp16
__device__ __align__(16) float  g_outs[CAP * D_DIM]; // GEMM2 result (no bias)

// ---------------- helpers ----------------
__device__ __forceinline__ uint32_t smem_u32(const void* p) {
    uint32_t a;
    asm("{ .reg .u64 t; cvta.to.shared.u64 t, %1; cvt.u32.u64 %0, t; }" : "=r"(a) : "l"(p));
    return a;
}
#define SWZ128(o) ((o) ^ (((o) >> 3) & 0x70))

#define LDSM4(r, addr) \
    asm volatile("ldmatrix.sync.aligned.m8n8.x4.shared.b16 {%0,%1,%2,%3}, [%4];" \
        : "=r"((r)[0]), "=r"((r)[1]), "=r"((r)[2]), "=r"((r)[3]) : "r"(addr))
#define LDSM2T(r, addr) \
    asm volatile("ldmatrix.sync.aligned.m8n8.x2.trans.shared.b16 {%0,%1}, [%2];" \
        : "=r"((r)[0]), "=r"((r)[1]) : "r"(addr))
#define MMA_F16(d, a, b) \
    asm volatile("mma.sync.aligned.m16n8k16.row.col.f32.f16.f16.f32 " \
        "{%0,%1,%2,%3}, {%4,%5,%6,%7}, {%8,%9}, {%0,%1,%2,%3};" \
        : "+f"((d)[0]), "+f"((d)[1]), "+f"((d)[2]), "+f"((d)[3]) \
        : "r"((a)[0]), "r"((a)[1]), "r"((a)[2]), "r"((a)[3]), "r"((b)[0]), "r"((b)[1]))
#define CP_ASYNC16(dst, src) \
    asm volatile("cp.async.cg.shared.global [%0], [%1], 16;" :: "r"(dst), "l"(src) : "memory")
#define CP_COMMIT() asm volatile("cp.async.commit_group;" ::: "memory")
#define CP_WAIT(n)  asm volatile("cp.async.wait_group %0;" :: "n"(n) : "memory")

__device__ __forceinline__ float gelu_tanh(float v) {
    float c = 0.7978845608028654f * (v + 0.044715f * v * v * v);
    return 0.5f * v * (1.0f + tanhf(c));
}

// pack 4 floats -> 2x half2 (uint2)
__device__ __forceinline__ uint2 pack4h(float4 f) {
    __half2 a = __float22half2_rn(make_float2(f.x, f.y));
    __half2 b = __float22half2_rn(make_float2(f.z, f.w));
    return make_uint2(*(uint32_t*)&a, *(uint32_t*)&b);
}

// ---------------- init ----------------
__global__ void init_kernel() {
    int i = blockIdx.x * 256 + threadIdx.x;
    if (i < CAP) g_slot_token[i] = -1;
    if (i < E_NUM) { g_counts[i] = 0; g_fill[i] = 0; }
}

// ---------------- router ----------------
__global__ __launch_bounds__(256) void router_kernel(const float* __restrict__ x,
                                                     const float* __restrict__ Wr) {
    __shared__ float sWr[D_DIM * E_NUM];
    __shared__ float sprobs[8][E_NUM];
    int tid = threadIdx.x;
    #pragma unroll
    for (int i = tid; i < D_DIM * E_NUM; i += 256) sWr[i] = Wr[i];
    __syncthreads();

    int warp = tid >> 5, lane = tid & 31;
    int t = blockIdx.x * 8 + warp;
    const float* xr = x + (size_t)t * D_DIM;

    float acc[E_NUM];
    #pragma unroll
    for (int e = 0; e < E_NUM; e++) acc[e] = 0.f;
    for (int k = lane; k < D_DIM; k += 32) {
        float xv = xr[k];
        const float* w = sWr + k * E_NUM;
        #pragma unroll
        for (int e = 0; e < E_NUM; e++) acc[e] += xv * w[e];
    }
    #pragma unroll
    for (int e = 0; e < E_NUM; e++) {
        float v = acc[e];
        #pragma unroll
        for (int off = 16; off >= 1; off >>= 1) v += __shfl_xor_sync(0xffffffffu, v, off);
        acc[e] = v;
    }
    if (lane == 0) {
        float mx = acc[0];
        #pragma unroll
        for (int e = 1; e < E_NUM; e++) mx = fmaxf(mx, acc[e]);
        float p[E_NUM]; float s = 0.f;
        #pragma unroll
        for (int e = 0; e < E_NUM; e++) { p[e] = expf(acc[e] - mx); s += p[e]; }
        float inv = 1.f / s;
        #pragma unroll
        for (int e = 0; e < E_NUM; e++) p[e] *= inv;
        int i0 = 0;
        #pragma unroll
        for (int e = 1; e < E_NUM; e++) if (p[e] > p[i0]) i0 = e;
        int i1 = -1;
        #pragma unroll
        for (int e = 0; e < E_NUM; e++) {
            if (e == i0) continue;
            if (i1 < 0 || p[e] > p[i1]) i1 = e;
        }
        float w0 = p[i0], w1 = p[i1];
        float wn = 1.f / (w0 + w1);
        g_tok_idx[2 * t + 0] = i0; g_tok_w[2 * t + 0] = w0 * wn;
        g_tok_idx[2 * t + 1] = i1; g_tok_w[2 * t + 1] = w1 * wn;
        atomicAdd(&g_counts[i0], 1);
        atomicAdd(&g_counts[i1], 1);
        #pragma unroll
        for (int e = 0; e < E_NUM; e++) sprobs[warp][e] = p[e];
    }
    __syncthreads();
    if (tid < E_NUM) {
        float s = 0.f;
        #pragma unroll
        for (int w = 0; w < 8; w++) s += sprobs[w][tid];
        g_probs_partial[blockIdx.x * E_NUM + tid] = s;
    }
}

// ---------------- scan ----------------
__global__ void scan_kernel(float* aux_out) {
    __shared__ float psum[E_NUM];
    int tid = threadIdx.x;
    if (tid < E_NUM) {
        float s = 0.f;
        for (int b = 0; b < RBLOCKS; b++) s += g_probs_partial[b * E_NUM + tid];
        psum[tid] = s;
    }
    __syncthreads();
    if (tid == 0) {
        int off = 0;
        for (int e = 0; e < E_NUM; e++) {
            g_offpad[e] = off;
            off += ((g_counts[e] + 127) / 128) * 128;
        }
        g_offpad[E_NUM] = off;
        for (int tile = 0; tile < MTILES; tile++) {
            int row = tile * 128;
            int ex = E_NUM - 1;
            for (int q = 0; q < E_NUM; q++) {
                if (row >= g_offpad[q] && row < g_offpad[q + 1]) { ex = q; break; }
            }
            g_tile_expert[tile] = ex;
        }
        float aux = 0.f;
        for (int e = 0; e < E_NUM; e++)
            aux += ((float)g_counts[e] / (float)T_TOK) * (psum[e] / (float)T_TOK);
        aux *= (float)E_NUM;
        if (aux_out) aux_out[0] = aux;
    }
}

// ---------------- assign ----------------
__global__ void assign_kernel() {
    int t = blockIdx.x * 256 + threadIdx.x;
    if (t >= T_TOK) return;
    #pragma unroll
    for (int j = 0; j < 2; j++) {
        int e = g_tok_idx[2 * t + j];
        int pos = atomicAdd(&g_fill[e], 1);
        int s = g_offpad[e] + pos;
        g_slot_token[s] = t;
        g_slot_expert[s] = e;
        g_slot_w[s] = g_tok_w[2 * t + j];
        g_token_slot[2 * t + j] = s;
    }
}

// ---------------- gather: xg[slot] -> fp16 ----------------
__global__ __launch_bounds__(128) void gather_kernel(const float* __restrict__ x,
                                                     const float* __restrict__ flow,
                                                     const float* __restrict__ avgq,
                                                     const float* __restrict__ deltas,
                                                     const float* __restrict__ Wf,
                                                     const float* __restrict__ Wd) {
    __shared__ float side[DF_DIM];
    int slot = blockIdx.x;
    int t = g_slot_token[slot];
    int d4 = threadIdx.x;  // 128 threads * 4 elems
    uint2* dsth = (uint2*)(g_ah + (size_t)slot * D_DIM + d4 * 4);
    if (t < 0) { *dsth = make_uint2(0u, 0u); return; }
    int e = g_slot_expert[slot];
    float4 v = ((const float4*)(x + (size_t)t * D_DIM))[d4];
    if (e == 0 || e == 4) {
        const float* srow = (e == 0 ? flow : deltas) + (size_t)t * DF_DIM;
        if (threadIdx.x < DF_DIM) side[threadIdx.x] = srow[threadIdx.x];
        __syncthreads();
        const float* W = (e == 0 ? Wf : Wd);
        int d0 = d4 * 4;
        #pragma unroll 8
        for (int k = 0; k < DF_DIM; k++) {
            float s = side[k];
            float4 w = *(const float4*)(W + (size_t)k * D_DIM + d0);
            v.x += s * w.x; v.y += s * w.y; v.z += s * w.z; v.w += s * w.w;
        }
    } else if (e == 3) {
        float4 q = ((const float4*)(avgq + (size_t)t * D_DIM))[d4];
        v.x += q.x; v.y += q.y; v.z += q.z; v.w += q.w;
    }
    *dsth = pack4h(v);
}

// ---------------- grouped GEMM via mma.sync m16n8k16 fp16 (single-term) ----------------
// Block: 512 thr = 16 warps (4m x 4n), warp tile 32x32, block tile 128x128, K-chunk 64.
// A: cp.async fp16, SMEM [m=128][128B = fp16 k0..63] SW128, non-trans ldmatrix.x4.
// B: fp32 weights converted fp16 in-flight, SMEM [k=64][256B n-major],
//    swizzle byte(k,Y) = k*256 + (Y ^ ((k&7)<<4)), ldmatrix.x2.trans.
template <int KTOT, bool FIRST>
__global__ __launch_bounds__(512) void gemm_mma(const float* __restrict__ Wsrc,
                                                const float* __restrict__ bias) {
    constexpr int NTOT = FIRST ? F_DIM : D_DIM;
    constexpr int NCH = KTOT / 64;
    extern __shared__ char dsm[];

    const int mtile = blockIdx.y;
    if (mtile * 128 >= g_offpad[E_NUM]) return;   // early-exit unused padded tiles

    const int tid = threadIdx.x;
    const int wid = tid >> 5, lane = tid & 31;
    const int wm = wid >> 2, wn = wid & 3;        // 4x4 warp grid, warp tile 32x32
    const int ntile = blockIdx.x;
    const int e = g_tile_expert[mtile];

    const __half* A = (FIRST ? g_ah : g_hh) + (size_t)(mtile * 128) * KTOT;
    const float* Bw = Wsrc + (size_t)e * KTOT * NTOT + ntile * 128;   // [k][n] fp32, n contig

    const uint32_t smb = smem_u32(dsm);

    // ---- A staging (cp.async): row r0 = tid>>2 (0..127), 2 x 16B units per thread.
    // Row bytes are contiguous in global (fp16 k-major); k-chunk c starts at halfs c*64.
    const int r0  = tid >> 2;
    const int u0  = tid & 3;              // units u0 and u0+4
    const __half* pA = A + (size_t)r0 * KTOT + u0 * 8;
    const uint32_t dA0 = SWZ128((uint32_t)(r0 * 128 + u0 * 16));
    const uint32_t dA1 = SWZ128((uint32_t)(r0 * 128 + (u0 + 4) * 16));

    // ---- B staging: krow = tid>>3 (0..63), seg = tid&7 covers floats [seg*16, seg*16+16).
    const int krow = tid >> 3;
    const int seg  = tid & 7;
    const float* pB = Bw + (size_t)krow * NTOT + seg * 16;
    const uint32_t dBrow = (uint32_t)(krow * 256);
    const uint32_t maskB = ((uint32_t)(krow & 7)) << 4;
    // 16B stores at: dBrow + ((seg*32 + {0,16}) ^ maskB)   [always < 256]

    float acc[2][4][4];
    #pragma unroll
    for (int mf = 0; mf < 2; mf++)
        #pragma unroll
        for (int nf = 0; nf < 4; nf++)
            #pragma unroll
            for (int k = 0; k < 4; k++) acc[mf][nf][k] = 0.f;

    // ---- prologue: chunk 0 -> buffer 0
    {
        CP_ASYNC16(smb + dA0, pA);
        CP_ASYNC16(smb + dA1, pA + 32);
        CP_COMMIT();
        char* bb = dsm + A_TILE_BYTES;
        float4 f0 = *(const float4*)(pB);
        float4 f1 = *(const float4*)(pB + 4);
        float4 f2 = *(const float4*)(pB + 8);
        float4 f3 = *(const float4*)(pB + 12);
        uint2 p0 = pack4h(f0), p1 = pack4h(f1), p2 = pack4h(f2), p3 = pack4h(f3);
        uint32_t o1 = dBrow + (((uint32_t)(seg * 32)) ^ maskB);
        uint32_t o2 = dBrow + (((uint32_t)(seg * 32 + 16)) ^ maskB);
        *(uint4*)(bb + o1) = make_uint4(p0.x, p0.y, p1.x, p1.y);
        *(uint4*)(bb + o2) = make_uint4(p2.x, p2.y, p3.x, p3.y);
        CP_WAIT(0);
    }
    __syncthreads();

    #pragma unroll 1
    for (int c = 0; c < NCH; c++) {
        const int buf = c & 1;
        float4 f0, f1, f2, f3;
        if (c + 1 < NCH) {
            const uint32_t nbA = smb + (buf ^ 1) * STAGE_BYTES;
            CP_ASYNC16(nbA + dA0, pA + (c + 1) * 64);
            CP_ASYNC16(nbA + dA1, pA + (c + 1) * 64 + 32);
            CP_COMMIT();
            const float* pBn = pB + (size_t)(c + 1) * 64 * NTOT;
            f0 = *(const float4*)(pBn);
            f1 = *(const float4*)(pBn + 4);
            f2 = *(const float4*)(pBn + 8);
            f3 = *(const float4*)(pBn + 12);
        }

        // ---- compute chunk c (4 k16 steps)
        const uint32_t At = smb + buf * STAGE_BYTES;
        const uint32_t Bt = At + A_TILE_BYTES;
        #pragma unroll
        for (int s = 0; s < 4; s++) {
            uint32_t ah[2][4];
            #pragma unroll
            for (int mf = 0; mf < 2; mf++) {
                int row = wm * 32 + mf * 16 + (lane & 15);
                int u = lane >> 4;
                uint32_t off = (uint32_t)(row * 128 + s * 32 + u * 16);
                LDSM4(ah[mf], At + SWZ128(off));
            }
            #pragma unroll
            for (int nf = 0; nf < 4; nf++) {
                uint32_t bh[2];
                int kk = s * 16 + (lane & 15);
                uint32_t boff = (uint32_t)(kk * 256) +
                                (((uint32_t)(wn * 64 + nf * 16)) ^ ((uint32_t)(lane & 7) << 4));
                LDSM2T(bh, Bt + boff);
                #pragma unroll
                for (int mf = 0; mf < 2; mf++)
                    MMA_F16(acc[mf][nf], ah[mf], bh);
            }
        }

        if (c + 1 < NCH) {
            char* nbb = dsm + (buf ^ 1) * STAGE_BYTES + A_TILE_BYTES;
            uint2 p0 = pack4h(f0), p1 = pack4h(f1), p2 = pack4h(f2), p3 = pack4h(f3);
            uint32_t o1 = dBrow + (((uint32_t)(seg * 32)) ^ maskB);
            uint32_t o2 = dBrow + (((uint32_t)(seg * 32 + 16)) ^ maskB);
            *(uint4*)(nbb + o1) = make_uint4(p0.x, p0.y, p1.x, p1.y);
            *(uint4*)(nbb + o2) = make_uint4(p2.x, p2.y, p3.x, p3.y);
            CP_WAIT(0);
        }
        __syncthreads();
    }

    // ---- epilogue
    #pragma unroll
    for (int mf = 0; mf < 2; mf++) {
        int row0 = mtile * 128 + wm * 32 + mf * 16 + (lane >> 2);
        int row1 = row0 + 8;
        #pragma unroll
        for (int nf = 0; nf < 4; nf++) {
            int n = ntile * 128 + wn * 32 + nf * 8 + 2 * (lane & 3);
            if (FIRST) {
                float b0v = bias[(size_t)e * NTOT + n];
                float b1v = bias[(size_t)e * NTOT + n + 1];
                #pragma unroll
                for (int h = 0; h < 2; h++) {
                    int row = h ? row1 : row0;
                    float v0 = gelu_tanh(acc[mf][nf][2 * h + 0] + b0v);
                    float v1 = gelu_tanh(acc[mf][nf][2 * h + 1] + b1v);
                    __half2 hv = __float22half2_rn(make_float2(v0, v1));
                    *(uint32_t*)(g_hh + (size_t)row * F_DIM + n) = *(uint32_t*)&hv;
                }
            } else {
                *(float2*)(g_outs + (size_t)row0 * D_DIM + n) =
                    make_float2(acc[mf][nf][0], acc[mf][nf][1]);
                *(float2*)(g_outs + (size_t)row1 * D_DIM + n) =
                    make_float2(acc[mf][nf][2], acc[mf][nf][3]);
            }
        }
    }
}

// ---------------- combine ----------------
__global__ __launch_bounds__(128) void combine_kernel(const float* __restrict__ b2,
                                                      float* __restrict__ out) {
    int t = blockIdx.x;
    int d4 = threadIdx.x;
    int s0 = g_token_slot[2 * t + 0];
    int s1 = g_token_slot[2 * t + 1];
    int e0 = g_slot_expert[s0], e1 = g_slot_expert[s1];
    float w0 = g_slot_w[s0], w1 = g_slot_w[s1];
    float4 o0 = ((const float4*)(g_outs + (size_t)s0 * D_DIM))[d4];
    float4 o1 = ((const float4*)(g_outs + (size_t)s1 * D_DIM))[d4];
    float4 c0 = ((const float4*)(b2 + (size_t)e0 * D_DIM))[d4];
    float4 c1 = ((const float4*)(b2 + (size_t)e1 * D_DIM))[d4];
    float4 r;
    r.x = w0 * (o0.x + c0.x) + w1 * (o1.x + c1.x);
    r.y = w0 * (o0.y + c0.y) + w1 * (o1.y + c1.y);
    r.z = w0 * (o0.z + c0.z) + w1 * (o1.z + c1.z);
    r.w = w0 * (o0.w + c0.w) + w1 * (o1.w + c1.w);
    ((float4*)(out + (size_t)t * D_DIM))[d4] = r;
}

// ---------------- launch ----------------
extern "C" void kernel_launch(void* const* d_in, const int* in_sizes, int n_in,
                              void* d_out, int out_size) {
    const float* x      = (const float*)d_in[0];
    const float* flow   = (const float*)d_in[1];
    const float* avgq   = (const float*)d_in[2];
    const float* deltas = (const float*)d_in[3];
    const float* Wr     = (const float*)d_in[4];
    const float* W1     = (const float*)d_in[5];
    const float* b1     = (const float*)d_in[6];
    const float* W2     = (const float*)d_in[7];
    const float* b2     = (const float*)d_in[8];
    const float* Wf     = (const float*)d_in[9];
    const float* Wd     = (const float*)d_in[10];
    float* out = (float*)d_out;

    float* aux_ptr = (out_size > T_TOK * D_DIM) ? (out + (size_t)T_TOK * D_DIM) : nullptr;

    cudaFuncSetAttribute(gemm_mma<D_DIM, true>,  cudaFuncAttributeMaxDynamicSharedMemorySize, DSMEM_BYTES);
    cudaFuncSetAttribute(gemm_mma<F_DIM, false>, cudaFuncAttributeMaxDynamicSharedMemorySize, DSMEM_BYTES);

    init_kernel<<<(CAP + 255) / 256, 256>>>();
    router_kernel<<<RBLOCKS, 256>>>(x, Wr);
    scan_kernel<<<1, 256>>>(aux_ptr);
    assign_kernel<<<(T_TOK + 255) / 256, 256>>>();
    gather_kernel<<<CAP, 128>>>(x, flow, avgq, deltas, Wf, Wd);
    gemm_mma<D_DIM, true><<<dim3(F_DIM / 128, MTILES), 512, DSMEM_BYTES>>>(W1, b1);
    gemm_mma<F_DIM, false><<<dim3(D_DIM / 128, MTILES), 512, DSMEM_BYTES>>>(W2, nullptr);
    combine_kernel<<<T_TOK, 128>>>(b2, out);
}

// round 12
// speedup vs baseline: 1.7907x; 1.1820x over previous
#include <cuda_runtime.h>
#include <cuda_fp16.h>
#include <math.h>
#include <stdint.h>

// Problem constants
#define T_TOK 4096
#define D_DIM 512
#define E_NUM 8
#define F_DIM 2048
#define DF_DIM 64
#define CAP   9216          // 72*128: 2T=8192 slots + worst-case per-expert 128-pad
#define MTILES 72
#define RBLOCKS 512
#define WELEM (E_NUM * D_DIM * F_DIM)   // 8.4M elements per weight tensor

// SMEM stage (K-chunk 64): A 16KB ([m=128][128B fp16 k0..63] SW128) + B 16KB ([k=64][256B n-major])
#define A_TILE_BYTES 16384
#define B_TILE_BYTES 16384
#define STAGE_BYTES (A_TILE_BYTES + B_TILE_BYTES)     // 32KB
#define DSMEM_BYTES (2*STAGE_BYTES)                    // 64KB double-buffered

// ---------------- scratch (device globals) — ~100 MB (< proven-safe 113 MB) ----------------
__device__ int   g_counts[E_NUM];
__device__ int   g_fill[E_NUM];
__device__ int   g_offpad[E_NUM + 1];
__device__ int   g_tile_expert[MTILES];
__device__ int   g_slot_token[CAP];
__device__ int   g_slot_expert[CAP];
__device__ float g_slot_w[CAP];
__device__ int   g_token_slot[T_TOK * 2];
__device__ int   g_tok_idx[T_TOK * 2];
__device__ float g_tok_w[T_TOK * 2];
__device__ float g_probs_partial[RBLOCKS * E_NUM];

__device__ __align__(16) __half g_ah[CAP * D_DIM];   // gathered x (+side), fp16
__device__ __align__(16) __half g_hh[CAP * F_DIM];   // gelu output, fp16
__device__ __align__(16) __half g_w1h[WELEM];        // W1 fp16, [E][D][F] (same layout)
__device__ __align__(16) __half g_w2h[WELEM];        // W2 fp16, [E][F][D]
__device__ __align__(16) float  g_outs[CAP * D_DIM]; // GEMM2 result (no bias)

// ---------------- helpers ----------------
__device__ __forceinline__ uint32_t smem_u32(const void* p) {
    uint32_t a;
    asm("{ .reg .u64 t; cvta.to.shared.u64 t, %1; cvt.u32.u64 %0, t; }" : "=r"(a) : "l"(p));
    return a;
}
#define SWZ128(o) ((o) ^ (((o) >> 3) & 0x70))

#define LDSM4(r, addr) \
    asm volatile("ldmatrix.sync.aligned.m8n8.x4.shared.b16 {%0,%1,%2,%3}, [%4];" \
        : "=r"((r)[0]), "=r"((r)[1]), "=r"((r)[2]), "=r"((r)[3]) : "r"(addr))
#define LDSM2T(r, addr) \
    asm volatile("ldmatrix.sync.aligned.m8n8.x2.trans.shared.b16 {%0,%1}, [%2];" \
        : "=r"((r)[0]), "=r"((r)[1]) : "r"(addr))
#define MMA_F16(d, a, b) \
    asm volatile("mma.sync.aligned.m16n8k16.row.col.f32.f16.f16.f32 " \
        "{%0,%1,%2,%3}, {%4,%5,%6,%7}, {%8,%9}, {%0,%1,%2,%3};" \
        : "+f"((d)[0]), "+f"((d)[1]), "+f"((d)[2]), "+f"((d)[3]) \
        : "r"((a)[0]), "r"((a)[1]), "r"((a)[2]), "r"((a)[3]), "r"((b)[0]), "r"((b)[1]))
#define CP_ASYNC16(dst, src) \
    asm volatile("cp.async.cg.shared.global [%0], [%1], 16;" :: "r"(dst), "l"(src) : "memory")
#define CP_COMMIT() asm volatile("cp.async.commit_group;" ::: "memory")
#define CP_WAIT(n)  asm volatile("cp.async.wait_group %0;" :: "n"(n) : "memory")

__device__ __forceinline__ float gelu_tanh(float v) {
    float c = 0.7978845608028654f * (v + 0.044715f * v * v * v);
    return 0.5f * v * (1.0f + tanhf(c));
}

// pack 4 floats -> 2x half2 (uint2)
__device__ __forceinline__ uint2 pack4h(float4 f) {
    __half2 a = __float22half2_rn(make_float2(f.x, f.y));
    __half2 b = __float22half2_rn(make_float2(f.z, f.w));
    return make_uint2(*(uint32_t*)&a, *(uint32_t*)&b);
}

// ---------------- init ----------------
__global__ void init_kernel() {
    int i = blockIdx.x * 256 + threadIdx.x;
    if (i < CAP) g_slot_token[i] = -1;
    if (i < E_NUM) { g_counts[i] = 0; g_fill[i] = 0; }
}

// ---------------- weight convert: fp32 -> fp16, same layout ----------------
__global__ __launch_bounds__(256) void wconv_kernel(const float* __restrict__ W,
                                                    __half* __restrict__ O) {
    int i = blockIdx.x * 256 + threadIdx.x;     // 8 elements per thread
    const float4* src = (const float4*)W + (size_t)i * 2;
    float4 a = src[0], b = src[1];
    uint2 pa = pack4h(a), pb = pack4h(b);
    ((uint4*)O)[i] = make_uint4(pa.x, pa.y, pb.x, pb.y);
}

// ---------------- router ----------------
__global__ __launch_bounds__(256) void router_kernel(const float* __restrict__ x,
                                                     const float* __restrict__ Wr) {
    __shared__ float sWr[D_DIM * E_NUM];
    __shared__ float sprobs[8][E_NUM];
    int tid = threadIdx.x;
    #pragma unroll
    for (int i = tid; i < D_DIM * E_NUM; i += 256) sWr[i] = Wr[i];
    __syncthreads();

    int warp = tid >> 5, lane = tid & 31;
    int t = blockIdx.x * 8 + warp;
    const float* xr = x + (size_t)t * D_DIM;

    float acc[E_NUM];
    #pragma unroll
    for (int e = 0; e < E_NUM; e++) acc[e] = 0.f;
    for (int k = lane; k < D_DIM; k += 32) {
        float xv = xr[k];
        const float* w = sWr + k * E_NUM;
        #pragma unroll
        for (int e = 0; e < E_NUM; e++) acc[e] += xv * w[e];
    }
    #pragma unroll
    for (int e = 0; e < E_NUM; e++) {
        float v = acc[e];
        #pragma unroll
        for (int off = 16; off >= 1; off >>= 1) v += __shfl_xor_sync(0xffffffffu, v, off);
        acc[e] = v;
    }
    if (lane == 0) {
        float mx = acc[0];
        #pragma unroll
        for (int e = 1; e < E_NUM; e++) mx = fmaxf(mx, acc[e]);
        float p[E_NUM]; float s = 0.f;
        #pragma unroll
        for (int e = 0; e < E_NUM; e++) { p[e] = expf(acc[e] - mx); s += p[e]; }
        float inv = 1.f / s;
        #pragma unroll
        for (int e = 0; e < E_NUM; e++) p[e] *= inv;
        int i0 = 0;
        #pragma unroll
        for (int e = 1; e < E_NUM; e++) if (p[e] > p[i0]) i0 = e;
        int i1 = -1;
        #pragma unroll
        for (int e = 0; e < E_NUM; e++) {
            if (e == i0) continue;
            if (i1 < 0 || p[e] > p[i1]) i1 = e;
        }
        float w0 = p[i0], w1 = p[i1];
        float wn = 1.f / (w0 + w1);
        g_tok_idx[2 * t + 0] = i0; g_tok_w[2 * t + 0] = w0 * wn;
        g_tok_idx[2 * t + 1] = i1; g_tok_w[2 * t + 1] = w1 * wn;
        atomicAdd(&g_counts[i0], 1);
        atomicAdd(&g_counts[i1], 1);
        #pragma unroll
        for (int e = 0; e < E_NUM; e++) sprobs[warp][e] = p[e];
    }
    __syncthreads();
    if (tid < E_NUM) {
        float s = 0.f;
        #pragma unroll
        for (int w = 0; w < 8; w++) s += sprobs[w][tid];
        g_probs_partial[blockIdx.x * E_NUM + tid] = s;
    }
}

// ---------------- scan ----------------
__global__ void scan_kernel(float* aux_out) {
    __shared__ float psum[E_NUM];
    int tid = threadIdx.x;
    if (tid < E_NUM) {
        float s = 0.f;
        for (int b = 0; b < RBLOCKS; b++) s += g_probs_partial[b * E_NUM + tid];
        psum[tid] = s;
    }
    __syncthreads();
    if (tid == 0) {
        int off = 0;
        for (int e = 0; e < E_NUM; e++) {
            g_offpad[e] = off;
            off += ((g_counts[e] + 127) / 128) * 128;
        }
        g_offpad[E_NUM] = off;
        for (int tile = 0; tile < MTILES; tile++) {
            int row = tile * 128;
            int ex = E_NUM - 1;
            for (int q = 0; q < E_NUM; q++) {
                if (row >= g_offpad[q] && row < g_offpad[q + 1]) { ex = q; break; }
            }
            g_tile_expert[tile] = ex;
        }
        float aux = 0.f;
        for (int e = 0; e < E_NUM; e++)
            aux += ((float)g_counts[e] / (float)T_TOK) * (psum[e] / (float)T_TOK);
        aux *= (float)E_NUM;
        if (aux_out) aux_out[0] = aux;
    }
}

// ---------------- assign ----------------
__global__ void assign_kernel() {
    int t = blockIdx.x * 256 + threadIdx.x;
    if (t >= T_TOK) return;
    #pragma unroll
    for (int j = 0; j < 2; j++) {
        int e = g_tok_idx[2 * t + j];
        int pos = atomicAdd(&g_fill[e], 1);
        int s = g_offpad[e] + pos;
        g_slot_token[s] = t;
        g_slot_expert[s] = e;
        g_slot_w[s] = g_tok_w[2 * t + j];
        g_token_slot[2 * t + j] = s;
    }
}

// ---------------- gather: xg[slot] -> fp16 ----------------
__global__ __launch_bounds__(128) void gather_kernel(const float* __restrict__ x,
                                                     const float* __restrict__ flow,
                                                     const float* __restrict__ avgq,
                                                     const float* __restrict__ deltas,
                                                     const float* __restrict__ Wf,
                                                     const float* __restrict__ Wd) {
    __shared__ float side[DF_DIM];
    int slot = blockIdx.x;
    int t = g_slot_token[slot];
    int d4 = threadIdx.x;  // 128 threads * 4 elems
    uint2* dsth = (uint2*)(g_ah + (size_t)slot * D_DIM + d4 * 4);
    if (t < 0) { *dsth = make_uint2(0u, 0u); return; }
    int e = g_slot_expert[slot];
    float4 v = ((const float4*)(x + (size_t)t * D_DIM))[d4];
    if (e == 0 || e == 4) {
        const float* srow = (e == 0 ? flow : deltas) + (size_t)t * DF_DIM;
        if (threadIdx.x < DF_DIM) side[threadIdx.x] = srow[threadIdx.x];
        __syncthreads();
        const float* W = (e == 0 ? Wf : Wd);
        int d0 = d4 * 4;
        #pragma unroll 8
        for (int k = 0; k < DF_DIM; k++) {
            float s = side[k];
            float4 w = *(const float4*)(W + (size_t)k * D_DIM + d0);
            v.x += s * w.x; v.y += s * w.y; v.z += s * w.z; v.w += s * w.w;
        }
    } else if (e == 3) {
        float4 q = ((const float4*)(avgq + (size_t)t * D_DIM))[d4];
        v.x += q.x; v.y += q.y; v.z += q.z; v.w += q.w;
    }
    *dsth = pack4h(v);
}

// ---------------- grouped GEMM via mma.sync m16n8k16 fp16 (single-term) ----------------
// Block: 256 thr = 8 warps (2m x 4n), warp tile 64x32, block tile 128x128, K-chunk 64.
// A: cp.async fp16, SMEM [m=128][128B = fp16 k0..63] SW128, non-trans ldmatrix.x4.
// B: cp.async pre-converted fp16 weights, SMEM [k=64][256B n-major],
//    swizzle byte(k,Y) = k*256 + (Y ^ ((k&7)<<4)), ldmatrix.x2.trans.
template <int KTOT, bool FIRST>
__global__ __launch_bounds__(256) void gemm_mma(const float* __restrict__ bias) {
    constexpr int NTOT = FIRST ? F_DIM : D_DIM;
    constexpr int NCH = KTOT / 64;
    extern __shared__ char dsm[];

    const int mtile = blockIdx.y;
    if (mtile * 128 >= g_offpad[E_NUM]) return;   // early-exit unused padded tiles

    const int tid = threadIdx.x;
    const int wid = tid >> 5, lane = tid & 31;
    const int wm = wid >> 2, wn = wid & 3;        // 2x4 warp grid, warp tile 64x32
    const int ntile = blockIdx.x;
    const int e = g_tile_expert[mtile];

    const __half* A  = (FIRST ? g_ah : g_hh) + (size_t)(mtile * 128) * KTOT;
    const __half* Bh = (FIRST ? g_w1h : g_w2h) + (size_t)e * KTOT * NTOT + ntile * 128;

    const uint32_t smb = smem_u32(dsm);

    // ---- A staging: 1024 16B-units/chunk, 4 per thread (2 threads/row, 4 units each).
    const int rA = tid >> 1;              // 0..127
    const int uA = (tid & 1) * 4;         // units uA..uA+3
    const __half* pA = A + (size_t)rA * KTOT + uA * 8;
    uint32_t dA[4];
    #pragma unroll
    for (int j = 0; j < 4; j++) dA[j] = SWZ128((uint32_t)(rA * 128 + (uA + j) * 16));

    // ---- B staging: 1024 16B-units/chunk, 4 per thread (4 threads/row, 4 units each).
    const int rB = tid >> 2;              // 0..63
    const int uB = (tid & 3) * 4;         // units uB..uB+3
    const __half* pB = Bh + (size_t)rB * NTOT + uB * 8;
    const uint32_t maskB = ((uint32_t)(rB & 7)) << 4;
    uint32_t dB[4];
    #pragma unroll
    for (int j = 0; j < 4; j++)
        dB[j] = (uint32_t)(rB * 256) + ((((uint32_t)(uB + j)) * 16) ^ maskB);

    float acc[4][4][4];
    #pragma unroll
    for (int mf = 0; mf < 4; mf++)
        #pragma unroll
        for (int nf = 0; nf < 4; nf++)
            #pragma unroll
            for (int k = 0; k < 4; k++) acc[mf][nf][k] = 0.f;

    // ---- prologue: chunk 0 -> buffer 0
    #pragma unroll
    for (int j = 0; j < 4; j++) {
        CP_ASYNC16(smb + dA[j], pA + j * 8);
        CP_ASYNC16(smb + A_TILE_BYTES + dB[j], pB + j * 8);
    }
    CP_COMMIT();
    CP_WAIT(0);
    __syncthreads();

    #pragma unroll 1
    for (int c = 0; c < NCH; c++) {
        const int buf = c & 1;
        if (c + 1 < NCH) {
            const uint32_t nb = smb + (buf ^ 1) * STAGE_BYTES;
            const __half* pAn = pA + (c + 1) * 64;
            const __half* pBn = pB + (size_t)(c + 1) * 64 * NTOT;
            #pragma unroll
            for (int j = 0; j < 4; j++) {
                CP_ASYNC16(nb + dA[j], pAn + j * 8);
                CP_ASYNC16(nb + A_TILE_BYTES + dB[j], pBn + j * 8);
            }
            CP_COMMIT();
        }

        // ---- compute chunk c (4 k16 steps)
        const uint32_t At = smb + buf * STAGE_BYTES;
        const uint32_t Bt = At + A_TILE_BYTES;
        #pragma unroll
        for (int s = 0; s < 4; s++) {
            uint32_t ah[4][4];
            #pragma unroll
            for (int mf = 0; mf < 4; mf++) {
                int row = wm * 64 + mf * 16 + (lane & 15);
                int u = lane >> 4;
                uint32_t off = (uint32_t)(row * 128 + s * 32 + u * 16);
                LDSM4(ah[mf], At + SWZ128(off));
            }
            #pragma unroll
            for (int nf = 0; nf < 4; nf++) {
                uint32_t bh[2];
                int kk = s * 16 + (lane & 15);
                uint32_t boff = (uint32_t)(kk * 256) +
                                (((uint32_t)(wn * 64 + nf * 16)) ^ ((uint32_t)(lane & 7) << 4));
                LDSM2T(bh, Bt + boff);
                #pragma unroll
                for (int mf = 0; mf < 4; mf++)
                    MMA_F16(acc[mf][nf], ah[mf], bh);
            }
        }

        if (c + 1 < NCH) CP_WAIT(0);
        __syncthreads();
    }

    // ---- epilogue
    #pragma unroll
    for (int mf = 0; mf < 4; mf++) {
        int row0 = mtile * 128 + wm * 64 + mf * 16 + (lane >> 2);
        int row1 = row0 + 8;
        #pragma unroll
        for (int nf = 0; nf < 4; nf++) {
            int n = ntile * 128 + wn * 32 + nf * 8 + 2 * (lane & 3);
            if (FIRST) {
                float b0v = bias[(size_t)e * NTOT + n];
                float b1v = bias[(size_t)e * NTOT + n + 1];
                #pragma unroll
                for (int h = 0; h < 2; h++) {
                    int row = h ? row1 : row0;
                    float v0 = gelu_tanh(acc[mf][nf][2 * h + 0] + b0v);
                    float v1 = gelu_tanh(acc[mf][nf][2 * h + 1] + b1v);
                    __half2 hv = __float22half2_rn(make_float2(v0, v1));
                    *(uint32_t*)(g_hh + (size_t)row * F_DIM + n) = *(uint32_t*)&hv;
                }
            } else {
                *(float2*)(g_outs + (size_t)row0 * D_DIM + n) =
                    make_float2(acc[mf][nf][0], acc[mf][nf][1]);
                *(float2*)(g_outs + (size_t)row1 * D_DIM + n) =
                    make_float2(acc[mf][nf][2], acc[mf][nf][3]);
            }
        }
    }
}

// ---------------- combine ----------------
__global__ __launch_bounds__(128) void combine_kernel(const float* __restrict__ b2,
                                                      float* __restrict__ out) {
    int t = blockIdx.x;
    int d4 = threadIdx.x;
    int s0 = g_token_slot[2 * t + 0];
    int s1 = g_token_slot[2 * t + 1];
    int e0 = g_slot_expert[s0], e1 = g_slot_expert[s1];
    float w0 = g_slot_w[s0], w1 = g_slot_w[s1];
    float4 o0 = ((const float4*)(g_outs + (size_t)s0 * D_DIM))[d4];
    float4 o1 = ((const float4*)(g_outs + (size_t)s1 * D_DIM))[d4];
    float4 c0 = ((const float4*)(b2 + (size_t)e0 * D_DIM))[d4];
    float4 c1 = ((const float4*)(b2 + (size_t)e1 * D_DIM))[d4];
    float4 r;
    r.x = w0 * (o0.x + c0.x) + w1 * (o1.x + c1.x);
    r.y = w0 * (o0.y + c0.y) + w1 * (o1.y + c1.y);
    r.z = w0 * (o0.z + c0.z) + w1 * (o1.z + c1.z);
    r.w = w0 * (o0.w + c0.w) + w1 * (o1.w + c1.w);
    ((float4*)(out + (size_t)t * D_DIM))[d4] = r;
}

// ---------------- launch ----------------
extern "C" void kernel_launch(void* const* d_in, const int* in_sizes, int n_in,
                              void* d_out, int out_size) {
    const float* x      = (const float*)d_in[0];
    const float* flow   = (const float*)d_in[1];
    const float* avgq   = (const float*)d_in[2];
    const float* deltas = (const float*)d_in[3];
    const float* Wr     = (const float*)d_in[4];
    const float* W1     = (const float*)d_in[5];
    const float* b1     = (const float*)d_in[6];
    const float* W2     = (const float*)d_in[7];
    const float* b2     = (const float*)d_in[8];
    const float* Wf     = (const float*)d_in[9];
    const float* Wd     = (const float*)d_in[10];
    float* out = (float*)d_out;

    float* aux_ptr = (out_size > T_TOK * D_DIM) ? (out + (size_t)T_TOK * D_DIM) : nullptr;

    __half *w1h_p, *w2h_p;
    cudaGetSymbolAddress((void**)&w1h_p, g_w1h);
    cudaGetSymbolAddress((void**)&w2h_p, g_w2h);

    cudaFuncSetAttribute(gemm_mma<D_DIM, true>,  cudaFuncAttributeMaxDynamicSharedMemorySize, DSMEM_BYTES);
    cudaFuncSetAttribute(gemm_mma<F_DIM, false>, cudaFuncAttributeMaxDynamicSharedMemorySize, DSMEM_BYTES);

    init_kernel<<<(CAP + 255) / 256, 256>>>();
    wconv_kernel<<<WELEM / (256 * 8), 256>>>(W1, w1h_p);
    wconv_kernel<<<WELEM / (256 * 8), 256>>>(W2, w2h_p);
    router_kernel<<<RBLOCKS, 256>>>(x, Wr);
    scan_kernel<<<1, 256>>>(aux_ptr);
    assign_kernel<<<(T_TOK + 255) / 256, 256>>>();
    gather_kernel<<<CAP, 128>>>(x, flow, avgq, deltas, Wf, Wd);
    gemm_mma<D_DIM, true><<<dim3(F_DIM / 128, MTILES), 256, DSMEM_BYTES>>>(b1);
    gemm_mma<F_DIM, false><<<dim3(D_DIM / 128, MTILES), 256, DSMEM_BYTES>>>(nullptr);
    combine_kernel<<<T_TOK, 128>>>(b2, out);
}

// round 13
// speedup vs baseline: 2.0334x; 1.1356x over previous
#include <cuda_runtime.h>
#include <cuda_fp16.h>
#include <math.h>
#include <stdint.h>

// Problem constants
#define T_TOK 4096
#define D_DIM 512
#define E_NUM 8
#define F_DIM 2048
#define DF_DIM 64
#define CAP   9216          // 72*128: 2T=8192 slots + worst-case per-expert 128-pad
#define MTILES 72
#define RBLOCKS 256         // router blocks (16 tokens each)
#define WELEM (E_NUM * D_DIM * F_DIM)   // 8.4M elements per weight tensor

// SMEM stage (K-chunk 64): A 16KB ([m=128][128B fp16 k0..63] SW128) + B 16KB ([k=64][256B n-major])
#define A_TILE_BYTES 16384
#define B_TILE_BYTES 16384
#define STAGE_BYTES (A_TILE_BYTES + B_TILE_BYTES)     // 32KB
#define DSMEM_BYTES (2*STAGE_BYTES)                    // 64KB double-buffered

// ---------------- scratch (device globals) — ~100 MB (< proven-safe 113 MB) ----------------
__device__ int   g_counts[E_NUM];
__device__ int   g_fill[E_NUM];
__device__ int   g_offpad[E_NUM + 1];
__device__ int   g_tile_expert[MTILES];
__device__ int   g_slot_token[CAP];
__device__ int   g_slot_expert[CAP];
__device__ float g_slot_w[CAP];
__device__ int   g_token_slot[T_TOK * 2];
__device__ int   g_tok_idx[T_TOK * 2];
__device__ float g_tok_w[T_TOK * 2];
__device__ float g_probs_partial[RBLOCKS * E_NUM];

__device__ __align__(16) __half g_ah[CAP * D_DIM];   // gathered x (+side), fp16
__device__ __align__(16) __half g_hh[CAP * F_DIM];   // gelu output, fp16
__device__ __align__(16) __half g_w1h[WELEM];        // W1 fp16, [E][D][F] (same layout)
__device__ __align__(16) __half g_w2h[WELEM];        // W2 fp16, [E][F][D]
__device__ __align__(16) float  g_outs[CAP * D_DIM]; // GEMM2 result (no bias)

// ---------------- helpers ----------------
__device__ __forceinline__ uint32_t smem_u32(const void* p) {
    uint32_t a;
    asm("{ .reg .u64 t; cvta.to.shared.u64 t, %1; cvt.u32.u64 %0, t; }" : "=r"(a) : "l"(p));
    return a;
}
#define SWZ128(o) ((o) ^ (((o) >> 3) & 0x70))

#define LDSM4(r, addr) \
    asm volatile("ldmatrix.sync.aligned.m8n8.x4.shared.b16 {%0,%1,%2,%3}, [%4];" \
        : "=r"((r)[0]), "=r"((r)[1]), "=r"((r)[2]), "=r"((r)[3]) : "r"(addr))
#define LDSM4T(r, addr) \
    asm volatile("ldmatrix.sync.aligned.m8n8.x4.trans.shared.b16 {%0,%1,%2,%3}, [%4];" \
        : "=r"((r)[0]), "=r"((r)[1]), "=r"((r)[2]), "=r"((r)[3]) : "r"(addr))
#define MMA_F16(d, a, b0, b1) \
    asm volatile("mma.sync.aligned.m16n8k16.row.col.f32.f16.f16.f32 " \
        "{%0,%1,%2,%3}, {%4,%5,%6,%7}, {%8,%9}, {%0,%1,%2,%3};" \
        : "+f"((d)[0]), "+f"((d)[1]), "+f"((d)[2]), "+f"((d)[3]) \
        : "r"((a)[0]), "r"((a)[1]), "r"((a)[2]), "r"((a)[3]), "r"(b0), "r"(b1))
#define CP_ASYNC16(dst, src) \
    asm volatile("cp.async.cg.shared.global [%0], [%1], 16;" :: "r"(dst), "l"(src) : "memory")
#define CP_COMMIT() asm volatile("cp.async.commit_group;" ::: "memory")
#define CP_WAIT(n)  asm volatile("cp.async.wait_group %0;" :: "n"(n) : "memory")

__device__ __forceinline__ float gelu_tanh(float v) {
    float c = 0.7978845608028654f * (v + 0.044715f * v * v * v);
    return 0.5f * v * (1.0f + tanhf(c));
}

// pack 4 floats -> 2x half2 (uint2)
__device__ __forceinline__ uint2 pack4h(float4 f) {
    __half2 a = __float22half2_rn(make_float2(f.x, f.y));
    __half2 b = __float22half2_rn(make_float2(f.z, f.w));
    return make_uint2(*(uint32_t*)&a, *(uint32_t*)&b);
}

// ---------------- init ----------------
__global__ void init_kernel() {
    int i = blockIdx.x * 256 + threadIdx.x;
    if (i < CAP) g_slot_token[i] = -1;
    if (i < E_NUM) { g_counts[i] = 0; g_fill[i] = 0; }
}

// ---------------- weight convert: fp32 -> fp16, same layout ----------------
__global__ __launch_bounds__(256) void wconv_kernel(const float* __restrict__ W,
                                                    __half* __restrict__ O) {
    int i = blockIdx.x * 256 + threadIdx.x;     // 8 elements per thread
    const float4* src = (const float4*)W + (size_t)i * 2;
    float4 a = src[0], b = src[1];
    uint2 pa = pack4h(a), pb = pack4h(b);
    ((uint4*)O)[i] = make_uint4(pa.x, pa.y, pb.x, pb.y);
}

// ---------------- router: 512 thr, 16 tokens/block ----------------
__global__ __launch_bounds__(512) void router_kernel(const float* __restrict__ x,
                                                     const float* __restrict__ Wr) {
    __shared__ float sWr[D_DIM * E_NUM];
    __shared__ float sprobs[16][E_NUM];
    int tid = threadIdx.x;
    #pragma unroll
    for (int i = tid; i < D_DIM * E_NUM; i += 512) sWr[i] = Wr[i];
    __syncthreads();

    int warp = tid >> 5, lane = tid & 31;
    int t = blockIdx.x * 16 + warp;
    const float* xr = x + (size_t)t * D_DIM;

    float acc[E_NUM];
    #pragma unroll
    for (int e = 0; e < E_NUM; e++) acc[e] = 0.f;
    for (int k = lane; k < D_DIM; k += 32) {
        float xv = xr[k];
        const float* w = sWr + k * E_NUM;
        #pragma unroll
        for (int e = 0; e < E_NUM; e++) acc[e] += xv * w[e];
    }
    #pragma unroll
    for (int e = 0; e < E_NUM; e++) {
        float v = acc[e];
        #pragma unroll
        for (int off = 16; off >= 1; off >>= 1) v += __shfl_xor_sync(0xffffffffu, v, off);
        acc[e] = v;
    }
    if (lane == 0) {
        float mx = acc[0];
        #pragma unroll
        for (int e = 1; e < E_NUM; e++) mx = fmaxf(mx, acc[e]);
        float p[E_NUM]; float s = 0.f;
        #pragma unroll
        for (int e = 0; e < E_NUM; e++) { p[e] = expf(acc[e] - mx); s += p[e]; }
        float inv = 1.f / s;
        #pragma unroll
        for (int e = 0; e < E_NUM; e++) p[e] *= inv;
        int i0 = 0;
        #pragma unroll
        for (int e = 1; e < E_NUM; e++) if (p[e] > p[i0]) i0 = e;
        int i1 = -1;
        #pragma unroll
        for (int e = 0; e < E_NUM; e++) {
            if (e == i0) continue;
            if (i1 < 0 || p[e] > p[i1]) i1 = e;
        }
        float w0 = p[i0], w1 = p[i1];
        float wn = 1.f / (w0 + w1);
        g_tok_idx[2 * t + 0] = i0; g_tok_w[2 * t + 0] = w0 * wn;
        g_tok_idx[2 * t + 1] = i1; g_tok_w[2 * t + 1] = w1 * wn;
        atomicAdd(&g_counts[i0], 1);
        atomicAdd(&g_counts[i1], 1);
        #pragma unroll
        for (int e = 0; e < E_NUM; e++) sprobs[warp][e] = p[e];
    }
    __syncthreads();
    if (tid < E_NUM) {
        float s = 0.f;
        #pragma unroll
        for (int w = 0; w < 16; w++) s += sprobs[w][tid];
        g_probs_partial[blockIdx.x * E_NUM + tid] = s;
    }
}

// ---------------- scan ----------------
__global__ void scan_kernel(float* aux_out) {
    __shared__ float psum[E_NUM];
    int tid = threadIdx.x;
    if (tid < E_NUM) {
        float s = 0.f;
        for (int b = 0; b < RBLOCKS; b++) s += g_probs_partial[b * E_NUM + tid];
        psum[tid] = s;
    }
    __syncthreads();
    if (tid == 0) {
        int off = 0;
        for (int e = 0; e < E_NUM; e++) {
            g_offpad[e] = off;
            off += ((g_counts[e] + 127) / 128) * 128;
        }
        g_offpad[E_NUM] = off;
        for (int tile = 0; tile < MTILES; tile++) {
            int row = tile * 128;
            int ex = E_NUM - 1;
            for (int q = 0; q < E_NUM; q++) {
                if (row >= g_offpad[q] && row < g_offpad[q + 1]) { ex = q; break; }
            }
            g_tile_expert[tile] = ex;
        }
        float aux = 0.f;
        for (int e = 0; e < E_NUM; e++)
            aux += ((float)g_counts[e] / (float)T_TOK) * (psum[e] / (float)T_TOK);
        aux *= (float)E_NUM;
        if (aux_out) aux_out[0] = aux;
    }
}

// ---------------- assign ----------------
__global__ void assign_kernel() {
    int t = blockIdx.x * 256 + threadIdx.x;
    if (t >= T_TOK) return;
    #pragma unroll
    for (int j = 0; j < 2; j++) {
        int e = g_tok_idx[2 * t + j];
        int pos = atomicAdd(&g_fill[e], 1);
        int s = g_offpad[e] + pos;
        g_slot_token[s] = t;
        g_slot_expert[s] = e;
        g_slot_w[s] = g_tok_w[2 * t + j];
        g_token_slot[2 * t + j] = s;
    }
}

// ---------------- gather: xg[slot] -> fp16 ----------------
__global__ __launch_bounds__(128) void gather_kernel(const float* __restrict__ x,
                                                     const float* __restrict__ flow,
                                                     const float* __restrict__ avgq,
                                                     const float* __restrict__ deltas,
                                                     const float* __restrict__ Wf,
                                                     const float* __restrict__ Wd) {
    __shared__ float side[DF_DIM];
    int slot = blockIdx.x;
    int t = g_slot_token[slot];
    int d4 = threadIdx.x;  // 128 threads * 4 elems
    uint2* dsth = (uint2*)(g_ah + (size_t)slot * D_DIM + d4 * 4);
    if (t < 0) { *dsth = make_uint2(0u, 0u); return; }
    int e = g_slot_expert[slot];
    float4 v = ((const float4*)(x + (size_t)t * D_DIM))[d4];
    if (e == 0 || e == 4) {
        const float* srow = (e == 0 ? flow : deltas) + (size_t)t * DF_DIM;
        if (threadIdx.x < DF_DIM) side[threadIdx.x] = srow[threadIdx.x];
        __syncthreads();
        const float* W = (e == 0 ? Wf : Wd);
        int d0 = d4 * 4;
        #pragma unroll 8
        for (int k = 0; k < DF_DIM; k++) {
            float s = side[k];
            float4 w = *(const float4*)(W + (size_t)k * D_DIM + d0);
            v.x += s * w.x; v.y += s * w.y; v.z += s * w.z; v.w += s * w.w;
        }
    } else if (e == 3) {
        float4 q = ((const float4*)(avgq + (size_t)t * D_DIM))[d4];
        v.x += q.x; v.y += q.y; v.z += q.z; v.w += q.w;
    }
    *dsth = pack4h(v);
}

// ---------------- grouped GEMM via mma.sync m16n8k16 fp16 (single-term) ----------------
// Block: 256 thr = 8 warps (2m x 4n), warp tile 64x32, block tile 128x128, K-chunk 64.
// A: cp.async fp16, SMEM [m=128][128B = fp16 k0..63] SW128, non-trans ldmatrix.x4.
// B: cp.async pre-converted fp16 weights, SMEM [k=64][256B n-major],
//    swizzle byte(k,Y) = k*256 + (Y ^ ((k&7)<<4)), ldmatrix.x4.trans (2 nf per instr).
template <int KTOT, bool FIRST>
__global__ __launch_bounds__(256) void gemm_mma(const float* __restrict__ bias) {
    constexpr int NTOT = FIRST ? F_DIM : D_DIM;
    constexpr int NCH = KTOT / 64;
    extern __shared__ char dsm[];

    const int mtile = blockIdx.y;
    if (mtile * 128 >= g_offpad[E_NUM]) return;   // early-exit unused padded tiles

    const int tid = threadIdx.x;
    const int wid = tid >> 5, lane = tid & 31;
    const int wm = wid >> 2, wn = wid & 3;        // 2x4 warp grid, warp tile 64x32
    const int ntile = blockIdx.x;
    const int e = g_tile_expert[mtile];

    const __half* A  = (FIRST ? g_ah : g_hh) + (size_t)(mtile * 128) * KTOT;
    const __half* Bh = (FIRST ? g_w1h : g_w2h) + (size_t)e * KTOT * NTOT + ntile * 128;

    const uint32_t smb = smem_u32(dsm);

    // ---- A staging: 1024 16B-units/chunk, 4 per thread (2 threads/row, 4 units each).
    const int rA = tid >> 1;              // 0..127
    const int uA = (tid & 1) * 4;         // units uA..uA+3
    const __half* pA = A + (size_t)rA * KTOT + uA * 8;
    uint32_t dA[4];
    #pragma unroll
    for (int j = 0; j < 4; j++) dA[j] = SWZ128((uint32_t)(rA * 128 + (uA + j) * 16));

    // ---- B staging: 1024 16B-units/chunk, 4 per thread (4 threads/row, 4 units each).
    const int rB = tid >> 2;              // 0..63
    const int uB = (tid & 3) * 4;         // units uB..uB+3
    const __half* pB = Bh + (size_t)rB * NTOT + uB * 8;
    const uint32_t maskB = ((uint32_t)(rB & 7)) << 4;
    uint32_t dB[4];
    #pragma unroll
    for (int j = 0; j < 4; j++)
        dB[j] = (uint32_t)(rB * 256) + ((((uint32_t)(uB + j)) * 16) ^ maskB);

    float acc[4][4][4];
    #pragma unroll
    for (int mf = 0; mf < 4; mf++)
        #pragma unroll
        for (int nf = 0; nf < 4; nf++)
            #pragma unroll
            for (int k = 0; k < 4; k++) acc[mf][nf][k] = 0.f;

    // ---- prologue: chunk 0 -> buffer 0
    #pragma unroll
    for (int j = 0; j < 4; j++) {
        CP_ASYNC16(smb + dA[j], pA + j * 8);
        CP_ASYNC16(smb + A_TILE_BYTES + dB[j], pB + j * 8);
    }
    CP_COMMIT();
    CP_WAIT(0);
    __syncthreads();

    #pragma unroll 1
    for (int c = 0; c < NCH; c++) {
        const int buf = c & 1;
        if (c + 1 < NCH) {
            const uint32_t nb = smb + (buf ^ 1) * STAGE_BYTES;
            const __half* pAn = pA + (c + 1) * 64;
            const __half* pBn = pB + (size_t)(c + 1) * 64 * NTOT;
            #pragma unroll
            for (int j = 0; j < 4; j++) {
                CP_ASYNC16(nb + dA[j], pAn + j * 8);
                CP_ASYNC16(nb + A_TILE_BYTES + dB[j], pBn + j * 8);
            }
            CP_COMMIT();
        }

        // ---- compute chunk c (4 k16 steps)
        const uint32_t At = smb + buf * STAGE_BYTES;
        const uint32_t Bt = At + A_TILE_BYTES;
        #pragma unroll
        for (int s = 0; s < 4; s++) {
            uint32_t ah[4][4];
            #pragma unroll
            for (int mf = 0; mf < 4; mf++) {
                int row = wm * 64 + mf * 16 + (lane & 15);
                int u = lane >> 4;
                uint32_t off = (uint32_t)(row * 128 + s * 32 + u * 16);
                LDSM4(ah[mf], At + SWZ128(off));
            }
            #pragma unroll
            for (int nfp = 0; nfp < 2; nfp++) {
                // x4 trans: lanes 0-7/8-15 -> nf=2*nfp (k0-7, k8-15); lanes 16-31 -> nf=2*nfp+1
                uint32_t bq[4];
                int u = lane >> 3;                       // 0..3
                int kk = s * 16 + (u & 1) * 8 + (lane & 7);
                uint32_t nunit = (uint32_t)(wn * 64 + (nfp * 2 + (u >> 1)) * 16);
                uint32_t boff = (uint32_t)(kk * 256) + (nunit ^ ((uint32_t)(kk & 7) << 4));
                LDSM4T(bq, Bt + boff);
                #pragma unroll
                for (int mf = 0; mf < 4; mf++) {
                    MMA_F16(acc[mf][nfp * 2 + 0], ah[mf], bq[0], bq[1]);
                    MMA_F16(acc[mf][nfp * 2 + 1], ah[mf], bq[2], bq[3]);
                }
            }
        }

        if (c + 1 < NCH) CP_WAIT(0);
        __syncthreads();
    }

    // ---- epilogue
    #pragma unroll
    for (int mf = 0; mf < 4; mf++) {
        int row0 = mtile * 128 + wm * 64 + mf * 16 + (lane >> 2);
        int row1 = row0 + 8;
        #pragma unroll
        for (int nf = 0; nf < 4; nf++) {
            int n = ntile * 128 + wn * 32 + nf * 8 + 2 * (lane & 3);
            if (FIRST) {
                float b0v = bias[(size_t)e * NTOT + n];
                float b1v = bias[(size_t)e * NTOT + n + 1];
                #pragma unroll
                for (int h = 0; h < 2; h++) {
                    int row = h ? row1 : row0;
                    float v0 = gelu_tanh(acc[mf][nf][2 * h + 0] + b0v);
                    float v1 = gelu_tanh(acc[mf][nf][2 * h + 1] + b1v);
                    __half2 hv = __float22half2_rn(make_float2(v0, v1));
                    *(uint32_t*)(g_hh + (size_t)row * F_DIM + n) = *(uint32_t*)&hv;
                }
            } else {
                *(float2*)(g_outs + (size_t)row0 * D_DIM + n) =
                    make_float2(acc[mf][nf][0], acc[mf][nf][1]);
                *(float2*)(g_outs + (size_t)row1 * D_DIM + n) =
                    make_float2(acc[mf][nf][2], acc[mf][nf][3]);
            }
        }
    }
}

// ---------------- combine ----------------
__global__ __launch_bounds__(128) void combine_kernel(const float* __restrict__ b2,
                                                      float* __restrict__ out) {
    int t = blockIdx.x;
    int d4 = threadIdx.x;
    int s0 = g_token_slot[2 * t + 0];
    int s1 = g_token_slot[2 * t + 1];
    int e0 = g_slot_expert[s0], e1 = g_slot_expert[s1];
    float w0 = g_slot_w[s0], w1 = g_slot_w[s1];
    float4 o0 = ((const float4*)(g_outs + (size_t)s0 * D_DIM))[d4];
    float4 o1 = ((const float4*)(g_outs + (size_t)s1 * D_DIM))[d4];
    float4 c0 = ((const float4*)(b2 + (size_t)e0 * D_DIM))[d4];
    float4 c1 = ((const float4*)(b2 + (size_t)e1 * D_DIM))[d4];
    float4 r;
    r.x = w0 * (o0.x + c0.x) + w1 * (o1.x + c1.x);
    r.y = w0 * (o0.y + c0.y) + w1 * (o1.y + c1.y);
    r.z = w0 * (o0.z + c0.z) + w1 * (o1.z + c1.z);
    r.w = w0 * (o0.w + c0.w) + w1 * (o1.w + c1.w);
    ((float4*)(out + (size_t)t * D_DIM))[d4] = r;
}

// ---------------- launch ----------------
extern "C" void kernel_launch(void* const* d_in, const int* in_sizes, int n_in,
                              void* d_out, int out_size) {
    const float* x      = (const float*)d_in[0];
    const float* flow   = (const float*)d_in[1];
    const float* avgq   = (const float*)d_in[2];
    const float* deltas = (const float*)d_in[3];
    const float* Wr     = (const float*)d_in[4];
    const float* W1     = (const float*)d_in[5];
    const float* b1     = (const float*)d_in[6];
    const float* W2     = (const float*)d_in[7];
    const float* b2     = (const float*)d_in[8];
    const float* Wf     = (const float*)d_in[9];
    const float* Wd     = (const float*)d_in[10];
    float* out = (float*)d_out;

    float* aux_ptr = (out_size > T_TOK * D_DIM) ? (out + (size_t)T_TOK * D_DIM) : nullptr;

    __half *w1h_p, *w2h_p;
    cudaGetSymbolAddress((void**)&w1h_p, g_w1h);
    cudaGetSymbolAddress((void**)&w2h_p, g_w2h);

    cudaFuncSetAttribute(gemm_mma<D_DIM, true>,  cudaFuncAttributeMaxDynamicSharedMemorySize, DSMEM_BYTES);
    cudaFuncSetAttribute(gemm_mma<F_DIM, false>, cudaFuncAttributeMaxDynamicSharedMemorySize, DSMEM_BYTES);

    init_kernel<<<(CAP + 255) / 256, 256>>>();
    wconv_kernel<<<WELEM / (256 * 8), 256>>>(W1, w1h_p);
    wconv_kernel<<<WELEM / (256 * 8), 256>>>(W2, w2h_p);
    router_kernel<<<RBLOCKS, 512>>>(x, Wr);
    scan_kernel<<<1, 256>>>(aux_ptr);
    assign_kernel<<<(T_TOK + 255) / 256, 256>>>();
    gather_kernel<<<CAP, 128>>>(x, flow, avgq, deltas, Wf, Wd);
    gemm_mma<D_DIM, true><<<dim3(F_DIM / 128, MTILES), 256, DSMEM_BYTES>>>(b1);
    gemm_mma<F_DIM, false><<<dim3(D_DIM / 128, MTILES), 256, DSMEM_BYTES>>>(nullptr);
    combine_kernel<<<T_TOK, 128>>>(b2, out);
}

// round 14
// speedup vs baseline: 2.1140x; 1.0396x over previous
#include <cuda_runtime.h>
#include <cuda_fp16.h>
#include <math.h>
#include <stdint.h>

// Problem constants
#define T_TOK 4096
#define D_DIM 512
#define E_NUM 8
#define F_DIM 2048
#define DF_DIM 64
#define CAP   9216          // 72*128: 2T=8192 slots + worst-case per-expert 128-pad
#define MTILES 72
#define RBLOCKS 256         // router blocks (16 tokens each)
#define WELEM (E_NUM * D_DIM * F_DIM)   // 8.4M elements per weight tensor

// SMEM stage (K-chunk 64): A 16KB ([m=128][128B fp16 k0..63] SW128) + B 16KB ([k=64][256B n-major])
#define A_TILE_BYTES 16384
#define B_TILE_BYTES 16384
#define STAGE_BYTES (A_TILE_BYTES + B_TILE_BYTES)     // 32KB
#define NSTAGE 3
#define DSMEM_BYTES (NSTAGE*STAGE_BYTES)               // 96KB triple-buffered

// ---------------- scratch (device globals) — ~100 MB (< proven-safe 113 MB) ----------------
__device__ int   g_counts[E_NUM];
__device__ int   g_fill[E_NUM];
__device__ int   g_offpad[E_NUM + 1];
__device__ int   g_tile_expert[MTILES];
__device__ int   g_slot_token[CAP];
__device__ int   g_slot_expert[CAP];
__device__ float g_slot_w[CAP];
__device__ int   g_token_slot[T_TOK * 2];
__device__ int   g_tok_idx[T_TOK * 2];
__device__ float g_tok_w[T_TOK * 2];
__device__ float g_probs_partial[RBLOCKS * E_NUM];

__device__ __align__(16) __half g_ah[CAP * D_DIM];   // gathered x (+side), fp16
__device__ __align__(16) __half g_hh[CAP * F_DIM];   // gelu output, fp16
__device__ __align__(16) __half g_w1h[WELEM];        // W1 fp16, [E][D][F] (same layout)
__device__ __align__(16) __half g_w2h[WELEM];        // W2 fp16, [E][F][D]
__device__ __align__(16) float  g_outs[CAP * D_DIM]; // GEMM2 result (no bias)

// ---------------- helpers ----------------
__device__ __forceinline__ uint32_t smem_u32(const void* p) {
    uint32_t a;
    asm("{ .reg .u64 t; cvta.to.shared.u64 t, %1; cvt.u32.u64 %0, t; }" : "=r"(a) : "l"(p));
    return a;
}
#define SWZ128(o) ((o) ^ (((o) >> 3) & 0x70))

#define LDSM4(r, addr) \
    asm volatile("ldmatrix.sync.aligned.m8n8.x4.shared.b16 {%0,%1,%2,%3}, [%4];" \
        : "=r"((r)[0]), "=r"((r)[1]), "=r"((r)[2]), "=r"((r)[3]) : "r"(addr))
#define LDSM4T(r, addr) \
    asm volatile("ldmatrix.sync.aligned.m8n8.x4.trans.shared.b16 {%0,%1,%2,%3}, [%4];" \
        : "=r"((r)[0]), "=r"((r)[1]), "=r"((r)[2]), "=r"((r)[3]) : "r"(addr))
#define MMA_F16(d, a, b0, b1) \
    asm volatile("mma.sync.aligned.m16n8k16.row.col.f32.f16.f16.f32 " \
        "{%0,%1,%2,%3}, {%4,%5,%6,%7}, {%8,%9}, {%0,%1,%2,%3};" \
        : "+f"((d)[0]), "+f"((d)[1]), "+f"((d)[2]), "+f"((d)[3]) \
        : "r"((a)[0]), "r"((a)[1]), "r"((a)[2]), "r"((a)[3]), "r"(b0), "r"(b1))
#define CP_ASYNC16(dst, src) \
    asm volatile("cp.async.cg.shared.global [%0], [%1], 16;" :: "r"(dst), "l"(src) : "memory")
#define CP_COMMIT() asm volatile("cp.async.commit_group;" ::: "memory")
#define CP_WAIT(n)  asm volatile("cp.async.wait_group %0;" :: "n"(n) : "memory")

__device__ __forceinline__ float gelu_tanh(float v) {
    float c = 0.7978845608028654f * (v + 0.044715f * v * v * v);
    return 0.5f * v * (1.0f + tanhf(c));
}

// pack 4 floats -> 2x half2 (uint2)
__device__ __forceinline__ uint2 pack4h(float4 f) {
    __half2 a = __float22half2_rn(make_float2(f.x, f.y));
    __half2 b = __float22half2_rn(make_float2(f.z, f.w));
    return make_uint2(*(uint32_t*)&a, *(uint32_t*)&b);
}

// ---------------- init ----------------
__global__ void init_kernel() {
    int i = blockIdx.x * 256 + threadIdx.x;
    if (i < CAP) g_slot_token[i] = -1;
    if (i < E_NUM) { g_counts[i] = 0; g_fill[i] = 0; }
}

// ---------------- weight convert: fp32 -> fp16, both tensors, same layout ----------------
__global__ __launch_bounds__(256) void wconv_kernel(const float* __restrict__ W1,
                                                    __half* __restrict__ O1,
                                                    const float* __restrict__ W2,
                                                    __half* __restrict__ O2) {
    const float* W = blockIdx.y ? W2 : W1;
    __half* O = blockIdx.y ? O2 : O1;
    int i = blockIdx.x * 256 + threadIdx.x;     // 8 elements per thread
    const float4* src = (const float4*)W + (size_t)i * 2;
    float4 a = src[0], b = src[1];
    uint2 pa = pack4h(a), pb = pack4h(b);
    ((uint4*)O)[i] = make_uint4(pa.x, pa.y, pb.x, pb.y);
}

// ---------------- router: 512 thr, 16 tokens/block, vectorized ----------------
__global__ __launch_bounds__(512) void router_kernel(const float* __restrict__ x,
                                                     const float* __restrict__ Wr) {
    __shared__ float sWrT[E_NUM * D_DIM];   // transposed: [e][k]
    __shared__ float sprobs[16][E_NUM];
    int tid = threadIdx.x;
    // transpose fill: read Wr[k][e] coalesced, write sWrT[e][k]
    #pragma unroll
    for (int i = tid; i < D_DIM * E_NUM; i += 512) {
        int k = i >> 3, e = i & 7;
        sWrT[e * D_DIM + k] = Wr[i];
    }
    __syncthreads();

    int warp = tid >> 5, lane = tid & 31;
    int t = blockIdx.x * 16 + warp;
    const float* xr = x + (size_t)t * D_DIM;

    float acc[E_NUM];
    #pragma unroll
    for (int e = 0; e < E_NUM; e++) acc[e] = 0.f;
    #pragma unroll
    for (int i = 0; i < D_DIM / 128; i++) {
        int k0 = lane * 4 + i * 128;
        float4 xv = *(const float4*)(xr + k0);
        float xs[4] = {xv.x, xv.y, xv.z, xv.w};
        #pragma unroll
        for (int e = 0; e < E_NUM; e++) {
            float4 wv = *(const float4*)(sWrT + e * D_DIM + k0);
            acc[e] += xs[0] * wv.x + xs[1] * wv.y + xs[2] * wv.z + xs[3] * wv.w;
        }
    }
    #pragma unroll
    for (int e = 0; e < E_NUM; e++) {
        float v = acc[e];
        #pragma unroll
        for (int off = 16; off >= 1; off >>= 1) v += __shfl_xor_sync(0xffffffffu, v, off);
        acc[e] = v;
    }
    if (lane == 0) {
        float mx = acc[0];
        #pragma unroll
        for (int e = 1; e < E_NUM; e++) mx = fmaxf(mx, acc[e]);
        float p[E_NUM]; float s = 0.f;
        #pragma unroll
        for (int e = 0; e < E_NUM; e++) { p[e] = expf(acc[e] - mx); s += p[e]; }
        float inv = 1.f / s;
        #pragma unroll
        for (int e = 0; e < E_NUM; e++) p[e] *= inv;
        int i0 = 0;
        #pragma unroll
        for (int e = 1; e < E_NUM; e++) if (p[e] > p[i0]) i0 = e;
        int i1 = -1;
        #pragma unroll
        for (int e = 0; e < E_NUM; e++) {
            if (e == i0) continue;
            if (i1 < 0 || p[e] > p[i1]) i1 = e;
        }
        float w0 = p[i0], w1 = p[i1];
        float wn = 1.f / (w0 + w1);
        g_tok_idx[2 * t + 0] = i0; g_tok_w[2 * t + 0] = w0 * wn;
        g_tok_idx[2 * t + 1] = i1; g_tok_w[2 * t + 1] = w1 * wn;
        atomicAdd(&g_counts[i0], 1);
        atomicAdd(&g_counts[i1], 1);
        #pragma unroll
        for (int e = 0; e < E_NUM; e++) sprobs[warp][e] = p[e];
    }
    __syncthreads();
    if (tid < E_NUM) {
        float s = 0.f;
        #pragma unroll
        for (int w = 0; w < 16; w++) s += sprobs[w][tid];
        g_probs_partial[blockIdx.x * E_NUM + tid] = s;
    }
}

// ---------------- scan ----------------
__global__ void scan_kernel(float* aux_out) {
    __shared__ float psum[E_NUM];
    int tid = threadIdx.x;
    if (tid < E_NUM) {
        float s = 0.f;
        for (int b = 0; b < RBLOCKS; b++) s += g_probs_partial[b * E_NUM + tid];
        psum[tid] = s;
    }
    __syncthreads();
    if (tid == 0) {
        int off = 0;
        for (int e = 0; e < E_NUM; e++) {
            g_offpad[e] = off;
            off += ((g_counts[e] + 127) / 128) * 128;
        }
        g_offpad[E_NUM] = off;
        for (int tile = 0; tile < MTILES; tile++) {
            int row = tile * 128;
            int ex = E_NUM - 1;
            for (int q = 0; q < E_NUM; q++) {
                if (row >= g_offpad[q] && row < g_offpad[q + 1]) { ex = q; break; }
            }
            g_tile_expert[tile] = ex;
        }
        float aux = 0.f;
        for (int e = 0; e < E_NUM; e++)
            aux += ((float)g_counts[e] / (float)T_TOK) * (psum[e] / (float)T_TOK);
        aux *= (float)E_NUM;
        if (aux_out) aux_out[0] = aux;
    }
}

// ---------------- assign ----------------
__global__ void assign_kernel() {
    int t = blockIdx.x * 256 + threadIdx.x;
    if (t >= T_TOK) return;
    #pragma unroll
    for (int j = 0; j < 2; j++) {
        int e = g_tok_idx[2 * t + j];
        int pos = atomicAdd(&g_fill[e], 1);
        int s = g_offpad[e] + pos;
        g_slot_token[s] = t;
        g_slot_expert[s] = e;
        g_slot_w[s] = g_tok_w[2 * t + j];
        g_token_slot[2 * t + j] = s;
    }
}

// ---------------- gather: xg[slot] -> fp16 ----------------
__global__ __launch_bounds__(128) void gather_kernel(const float* __restrict__ x,
                                                     const float* __restrict__ flow,
                                                     const float* __restrict__ avgq,
                                                     const float* __restrict__ deltas,
                                                     const float* __restrict__ Wf,
                                                     const float* __restrict__ Wd) {
    __shared__ float side[DF_DIM];
    int slot = blockIdx.x;
    int t = g_slot_token[slot];
    int d4 = threadIdx.x;  // 128 threads * 4 elems
    uint2* dsth = (uint2*)(g_ah + (size_t)slot * D_DIM + d4 * 4);
    if (t < 0) { *dsth = make_uint2(0u, 0u); return; }
    int e = g_slot_expert[slot];
    float4 v = ((const float4*)(x + (size_t)t * D_DIM))[d4];
    if (e == 0 || e == 4) {
        const float* srow = (e == 0 ? flow : deltas) + (size_t)t * DF_DIM;
        if (threadIdx.x < DF_DIM) side[threadIdx.x] = srow[threadIdx.x];
        __syncthreads();
        const float* W = (e == 0 ? Wf : Wd);
        int d0 = d4 * 4;
        #pragma unroll 8
        for (int k = 0; k < DF_DIM; k++) {
            float s = side[k];
            float4 w = *(const float4*)(W + (size_t)k * D_DIM + d0);
            v.x += s * w.x; v.y += s * w.y; v.z += s * w.z; v.w += s * w.w;
        }
    } else if (e == 3) {
        float4 q = ((const float4*)(avgq + (size_t)t * D_DIM))[d4];
        v.x += q.x; v.y += q.y; v.z += q.z; v.w += q.w;
    }
    *dsth = pack4h(v);
}

// ---------------- grouped GEMM via mma.sync m16n8k16 fp16 (single-term) ----------------
// Block: 256 thr = 8 warps (2m x 4n), warp tile 64x32, block tile 128x128, K-chunk 64.
// 3-stage cp.async pipeline: wait_group(1) -> sync -> issue c+2 -> compute c.
// A: SMEM [m=128][128B fp16 k0..63] SW128, non-trans ldmatrix.x4.
// B: SMEM [k=64][256B n-major], swizzle byte(k,Y) = k*256 + (Y ^ ((k&7)<<4)), ldmatrix.x4.trans.
template <int KTOT, bool FIRST>
__global__ __launch_bounds__(256) void gemm_mma(const float* __restrict__ bias) {
    constexpr int NTOT = FIRST ? F_DIM : D_DIM;
    constexpr int NCH = KTOT / 64;
    extern __shared__ char dsm[];

    const int mtile = blockIdx.y;
    if (mtile * 128 >= g_offpad[E_NUM]) return;   // early-exit unused padded tiles

    const int tid = threadIdx.x;
    const int wid = tid >> 5, lane = tid & 31;
    const int wm = wid >> 2, wn = wid & 3;        // 2x4 warp grid, warp tile 64x32
    const int ntile = blockIdx.x;
    const int e = g_tile_expert[mtile];

    const __half* A  = (FIRST ? g_ah : g_hh) + (size_t)(mtile * 128) * KTOT;
    const __half* Bh = (FIRST ? g_w1h : g_w2h) + (size_t)e * KTOT * NTOT + ntile * 128;

    const uint32_t smb = smem_u32(dsm);

    // ---- A staging: 1024 16B-units/chunk, 4 per thread (2 threads/row, 4 units each).
    const int rA = tid >> 1;              // 0..127
    const int uA = (tid & 1) * 4;         // units uA..uA+3
    const __half* pA = A + (size_t)rA * KTOT + uA * 8;
    uint32_t dA[4];
    #pragma unroll
    for (int j = 0; j < 4; j++) dA[j] = SWZ128((uint32_t)(rA * 128 + (uA + j) * 16));

    // ---- B staging: 1024 16B-units/chunk, 4 per thread (4 threads/row, 4 units each).
    const int rB = tid >> 2;              // 0..63
    const int uB = (tid & 3) * 4;         // units uB..uB+3
    const __half* pB = Bh + (size_t)rB * NTOT + uB * 8;
    const uint32_t maskB = ((uint32_t)(rB & 7)) << 4;
    uint32_t dB[4];
    #pragma unroll
    for (int j = 0; j < 4; j++)
        dB[j] = (uint32_t)(rB * 256) + ((((uint32_t)(uB + j)) * 16) ^ maskB);

    float acc[4][4][4];
    #pragma unroll
    for (int mf = 0; mf < 4; mf++)
        #pragma unroll
        for (int nf = 0; nf < 4; nf++)
            #pragma unroll
            for (int k = 0; k < 4; k++) acc[mf][nf][k] = 0.f;

    // ---- prologue: issue chunks 0 and 1
    #pragma unroll
    for (int j = 0; j < 4; j++) {
        CP_ASYNC16(smb + dA[j], pA + j * 8);
        CP_ASYNC16(smb + A_TILE_BYTES + dB[j], pB + j * 8);
    }
    CP_COMMIT();
    {
        const uint32_t s1 = smb + STAGE_BYTES;
        const __half* pA1 = pA + 64;
        const __half* pB1 = pB + (size_t)64 * NTOT;
        #pragma unroll
        for (int j = 0; j < 4; j++) {
            CP_ASYNC16(s1 + dA[j], pA1 + j * 8);
            CP_ASYNC16(s1 + A_TILE_BYTES + dB[j], pB1 + j * 8);
        }
        CP_COMMIT();
    }

    int bufc = 0;   // buffer holding chunk c
    #pragma unroll 1
    for (int c = 0; c < NCH; c++) {
        if (c + 1 < NCH) CP_WAIT(1); else CP_WAIT(0);
        __syncthreads();
        if (c + 2 < NCH) {
            int bufl = bufc + 2; if (bufl >= NSTAGE) bufl -= NSTAGE;
            const uint32_t nb = smb + bufl * STAGE_BYTES;
            const __half* pAn = pA + (c + 2) * 64;
            const __half* pBn = pB + (size_t)(c + 2) * 64 * NTOT;
            #pragma unroll
            for (int j = 0; j < 4; j++) {
                CP_ASYNC16(nb + dA[j], pAn + j * 8);
                CP_ASYNC16(nb + A_TILE_BYTES + dB[j], pBn + j * 8);
            }
            CP_COMMIT();
        }

        // ---- compute chunk c (4 k16 steps)
        const uint32_t At = smb + bufc * STAGE_BYTES;
        const uint32_t Bt = At + A_TILE_BYTES;
        #pragma unroll
        for (int s = 0; s < 4; s++) {
            uint32_t ah[4][4];
            #pragma unroll
            for (int mf = 0; mf < 4; mf++) {
                int row = wm * 64 + mf * 16 + (lane & 15);
                int u = lane >> 4;
                uint32_t off = (uint32_t)(row * 128 + s * 32 + u * 16);
                LDSM4(ah[mf], At + SWZ128(off));
            }
            #pragma unroll
            for (int nfp = 0; nfp < 2; nfp++) {
                // x4 trans: lanes 0-7/8-15 -> nf=2*nfp (k0-7, k8-15); lanes 16-31 -> nf=2*nfp+1
                uint32_t bq[4];
                int u = lane >> 3;                       // 0..3
                int kk = s * 16 + (u & 1) * 8 + (lane & 7);
                uint32_t nunit = (uint32_t)(wn * 64 + (nfp * 2 + (u >> 1)) * 16);
                uint32_t boff = (uint32_t)(kk * 256) + (nunit ^ ((uint32_t)(kk & 7) << 4));
                LDSM4T(bq, Bt + boff);
                #pragma unroll
                for (int mf = 0; mf < 4; mf++) {
                    MMA_F16(acc[mf][nfp * 2 + 0], ah[mf], bq[0], bq[1]);
                    MMA_F16(acc[mf][nfp * 2 + 1], ah[mf], bq[2], bq[3]);
                }
            }
        }
        bufc = (bufc == NSTAGE - 1) ? 0 : bufc + 1;
    }

    // ---- epilogue
    #pragma unroll
    for (int mf = 0; mf < 4; mf++) {
        int row0 = mtile * 128 + wm * 64 + mf * 16 + (lane >> 2);
        int row1 = row0 + 8;
        #pragma unroll
        for (int nf = 0; nf < 4; nf++) {
            int n = ntile * 128 + wn * 32 + nf * 8 + 2 * (lane & 3);
            if (FIRST) {
                float b0v = bias[(size_t)e * NTOT + n];
                float b1v = bias[(size_t)e * NTOT + n + 1];
                #pragma unroll
                for (int h = 0; h < 2; h++) {
                    int row = h ? row1 : row0;
                    float v0 = gelu_tanh(acc[mf][nf][2 * h + 0] + b0v);
                    float v1 = gelu_tanh(acc[mf][nf][2 * h + 1] + b1v);
                    __half2 hv = __float22half2_rn(make_float2(v0, v1));
                    *(uint32_t*)(g_hh + (size_t)row * F_DIM + n) = *(uint32_t*)&hv;
                }
            } else {
                *(float2*)(g_outs + (size_t)row0 * D_DIM + n) =
                    make_float2(acc[mf][nf][0], acc[mf][nf][1]);
                *(float2*)(g_outs + (size_t)row1 * D_DIM + n) =
                    make_float2(acc[mf][nf][2], acc[mf][nf][3]);
            }
        }
    }
}

// ---------------- combine ----------------
__global__ __launch_bounds__(128) void combine_kernel(const float* __restrict__ b2,
                                                      float* __restrict__ out) {
    int t = blockIdx.x;
    int d4 = threadIdx.x;
    int s0 = g_token_slot[2 * t + 0];
    int s1 = g_token_slot[2 * t + 1];
    int e0 = g_slot_expert[s0], e1 = g_slot_expert[s1];
    float w0 = g_slot_w[s0], w1 = g_slot_w[s1];
    float4 o0 = ((const float4*)(g_outs + (size_t)s0 * D_DIM))[d4];
    float4 o1 = ((const float4*)(g_outs + (size_t)s1 * D_DIM))[d4];
    float4 c0 = ((const float4*)(b2 + (size_t)e0 * D_DIM))[d4];
    float4 c1 = ((const float4*)(b2 + (size_t)e1 * D_DIM))[d4];
    float4 r;
    r.x = w0 * (o0.x + c0.x) + w1 * (o1.x + c1.x);
    r.y = w0 * (o0.y + c0.y) + w1 * (o1.y + c1.y);
    r.z = w0 * (o0.z + c0.z) + w1 * (o1.z + c1.z);
    r.w = w0 * (o0.w + c0.w) + w1 * (o1.w + c1.w);
    ((float4*)(out + (size_t)t * D_DIM))[d4] = r;
}

// ---------------- launch ----------------
extern "C" void kernel_launch(void* const* d_in, const int* in_sizes, int n_in,
                              void* d_out, int out_size) {
    const float* x      = (const float*)d_in[0];
    const float* flow   = (const float*)d_in[1];
    const float* avgq   = (const float*)d_in[2];
    const float* deltas = (const float*)d_in[3];
    const float* Wr     = (const float*)d_in[4];
    const float* W1     = (const float*)d_in[5];
    const float* b1     = (const float*)d_in[6];
    const float* W2     = (const float*)d_in[7];
    const float* b2     = (const float*)d_in[8];
    const float* Wf     = (const float*)d_in[9];
    const float* Wd     = (const float*)d_in[10];
    float* out = (float*)d_out;

    float* aux_ptr = (out_size > T_TOK * D_DIM) ? (out + (size_t)T_TOK * D_DIM) : nullptr;

    __half *w1h_p, *w2h_p;
    cudaGetSymbolAddress((void**)&w1h_p, g_w1h);
    cudaGetSymbolAddress((void**)&w2h_p, g_w2h);

    cudaFuncSetAttribute(gemm_mma<D_DIM, true>,  cudaFuncAttributeMaxDynamicSharedMemorySize, DSMEM_BYTES);
    cudaFuncSetAttribute(gemm_mma<F_DIM, false>, cudaFuncAttributeMaxDynamicSharedMemorySize, DSMEM_BYTES);

    init_kernel<<<(CAP + 255) / 256, 256>>>();
    wconv_kernel<<<dim3(WELEM / (256 * 8), 2), 256>>>(W1, w1h_p, W2, w2h_p);
    router_kernel<<<RBLOCKS, 512>>>(x, Wr);
    scan_kernel<<<1, 256>>>(aux_ptr);
    assign_kernel<<<(T_TOK + 255) / 256, 256>>>();
    gather_kernel<<<CAP, 128>>>(x, flow, avgq, deltas, Wf, Wd);
    gemm_mma<D_DIM, true><<<dim3(F_DIM / 128, MTILES), 256, DSMEM_BYTES>>>(b1);
    gemm_mma<F_DIM, false><<<dim3(D_DIM / 128, MTILES), 256, DSMEM_BYTES>>>(nullptr);
    combine_kernel<<<T_TOK, 128>>>(b2, out);
}